// round 4
// baseline (speedup 1.0000x reference)
#include <cuda_runtime.h>
#include <math.h>

// Problem constants (fixed shapes for this problem instance)
#define BATCH   2
#define SEQ     2048
#define CDIM    2048
#define NHEAD   16
#define NKV     4
#define HDIM    128
#define MROWS   (BATCH * SEQ)          // 4096
#define KVDIM   (NKV * HDIM)           // 512

// GEMM tiling
#define BM 128
#define BN 128
#define BK 8
#define TM 8
#define TN 8
// threads per block = (BM/TM)*(BN/TN) = 256

typedef unsigned long long u64;

// ---------------------------------------------------------------------------
// Packed fp32x2 helpers (Blackwell sm_100+: SASS FFMA2 — 2x fp32 throughput,
// bit-identical to two scalar IEEE fp32 FMAs). ptxas never emits these from
// C++; PTX inline asm required.
// ---------------------------------------------------------------------------
__device__ __forceinline__ u64 pack2(float lo, float hi) {
    u64 r;
    asm("mov.b64 %0, {%1, %2};" : "=l"(r) : "r"(__float_as_uint(lo)), "r"(__float_as_uint(hi)));
    return r;
}
__device__ __forceinline__ u64 ffma2(u64 a, u64 b, u64 c) {
    u64 d;
    asm("fma.rn.f32x2 %0, %1, %2, %3;" : "=l"(d) : "l"(a), "l"(b), "l"(c));
    return d;
}
__device__ __forceinline__ void unpack2(u64 v, float& lo, float& hi) {
    unsigned int l, h;
    asm("mov.b64 {%0, %1}, %2;" : "=r"(l), "=r"(h) : "l"(v));
    lo = __uint_as_float(l);
    hi = __uint_as_float(h);
}

// ---------------------------------------------------------------------------
// Static device scratch (allocation-free rule: __device__ globals)
// ---------------------------------------------------------------------------
__device__ float g_q[(size_t)MROWS * CDIM];              // 32 MB   [B*T, 16*128]
__device__ float g_k[(size_t)MROWS * KVDIM];             // 8 MB    [B*T, 4*128]
__device__ float g_v[(size_t)MROWS * KVDIM];             // 8 MB
__device__ float g_s[(size_t)BATCH * NHEAD * SEQ * SEQ]; // 537 MB  scores per (b,h)
__device__ float g_att[(size_t)MROWS * CDIM];            // 32 MB   attention out

// ---------------------------------------------------------------------------
// Core NT GEMM tile: C[BM x BN] = alpha * A[BM x K] * B[BN x K]^T
// FFMA2-packed microkernel: acc held as 8x4 b64 pairs.
// ---------------------------------------------------------------------------
__device__ __forceinline__ void gemm_core_nt(
    const float* __restrict__ A, int lda,
    const float* __restrict__ B, int ldb,
    float* __restrict__ C, int ldc,
    int K, float alpha)
{
    __shared__ float As[BK][BM];
    __shared__ float Bs[BK][BN];

    const int tid  = threadIdx.x;
    const int tx   = tid & 15;        // N sub-tile index
    const int ty   = tid >> 4;        // M sub-tile index
    const int lrow = tid >> 1;        // 0..127  (row to load)
    const int lcol = (tid & 1) << 2;  // 0 or 4  (col group to load)

    const float* Ap = A + (size_t)blockIdx.y * BM * lda + (size_t)lrow * lda + lcol;
    const float* Bp = B + (size_t)blockIdx.x * BN * ldb + (size_t)lrow * ldb + lcol;

    u64 acc2[TM][TN / 2];
#pragma unroll
    for (int i = 0; i < TM; i++)
#pragma unroll
        for (int j = 0; j < TN / 2; j++) acc2[i][j] = 0ull;

    float4 a4 = *reinterpret_cast<const float4*>(Ap);
    float4 b4 = *reinterpret_cast<const float4*>(Bp);

    for (int k0 = 0; k0 < K; k0 += BK) {
        As[lcol + 0][lrow] = a4.x; As[lcol + 1][lrow] = a4.y;
        As[lcol + 2][lrow] = a4.z; As[lcol + 3][lrow] = a4.w;
        Bs[lcol + 0][lrow] = b4.x; Bs[lcol + 1][lrow] = b4.y;
        Bs[lcol + 2][lrow] = b4.z; Bs[lcol + 3][lrow] = b4.w;
        __syncthreads();

        if (k0 + BK < K) {  // register prefetch of next tile
            a4 = *reinterpret_cast<const float4*>(Ap + k0 + BK);
            b4 = *reinterpret_cast<const float4*>(Bp + k0 + BK);
        }

#pragma unroll
        for (int kk = 0; kk < BK; kk++) {
            const float4* arow = reinterpret_cast<const float4*>(&As[kk][ty * TM]);
            float4 ara = arow[0], arb = arow[1];
            u64 a2[TM];
            a2[0] = pack2(ara.x, ara.x); a2[1] = pack2(ara.y, ara.y);
            a2[2] = pack2(ara.z, ara.z); a2[3] = pack2(ara.w, ara.w);
            a2[4] = pack2(arb.x, arb.x); a2[5] = pack2(arb.y, arb.y);
            a2[6] = pack2(arb.z, arb.z); a2[7] = pack2(arb.w, arb.w);

            const u64* brow = reinterpret_cast<const u64*>(&Bs[kk][tx * TN]);
            u64 b2[TN / 2];
#pragma unroll
            for (int j = 0; j < TN / 2; j++) b2[j] = brow[j];

#pragma unroll
            for (int i = 0; i < TM; i++)
#pragma unroll
                for (int j = 0; j < TN / 2; j++)
                    acc2[i][j] = ffma2(a2[i], b2[j], acc2[i][j]);
        }
        __syncthreads();
    }

    float* Cp = C + (size_t)blockIdx.y * BM * ldc + (size_t)blockIdx.x * BN;
#pragma unroll
    for (int i = 0; i < TM; i++) {
        float* crow = Cp + (size_t)(ty * TM + i) * ldc + tx * TN;
#pragma unroll
        for (int j = 0; j < TN / 2; j += 2) {
            float4 v4;
            unpack2(acc2[i][j],     v4.x, v4.y);
            unpack2(acc2[i][j + 1], v4.z, v4.w);
            v4.x *= alpha; v4.y *= alpha; v4.z *= alpha; v4.w *= alpha;
            *reinterpret_cast<float4*>(crow + j * 2) = v4;
        }
    }
}

// ---------------------------------------------------------------------------
// Core NN GEMM tile: C[BM x 128] = A[BM x K] * B[K x 128]
// Used for P @ V (N = HDIM = 128, single BN tile; blockIdx.x unused).
// ---------------------------------------------------------------------------
__device__ __forceinline__ void gemm_core_nn(
    const float* __restrict__ A, int lda,
    const float* __restrict__ B, int ldb,
    float* __restrict__ C, int ldc,
    int K)
{
    __shared__ float As[BK][BM];
    __shared__ float Bs[BK][BN];

    const int tid  = threadIdx.x;
    const int tx   = tid & 15;
    const int ty   = tid >> 4;
    const int lrow = tid >> 1;
    const int lcol = (tid & 1) << 2;
    const int brow = tid >> 5;         // 0..7
    const int bcol = (tid & 31) << 2;  // 0..124

    const float* Ap = A + (size_t)blockIdx.y * BM * lda + (size_t)lrow * lda + lcol;
    const float* Bp = B + (size_t)brow * ldb + bcol;

    u64 acc2[TM][TN / 2];
#pragma unroll
    for (int i = 0; i < TM; i++)
#pragma unroll
        for (int j = 0; j < TN / 2; j++) acc2[i][j] = 0ull;

    float4 a4 = *reinterpret_cast<const float4*>(Ap);
    float4 b4 = *reinterpret_cast<const float4*>(Bp);

    for (int k0 = 0; k0 < K; k0 += BK) {
        As[lcol + 0][lrow] = a4.x; As[lcol + 1][lrow] = a4.y;
        As[lcol + 2][lrow] = a4.z; As[lcol + 3][lrow] = a4.w;
        *reinterpret_cast<float4*>(&Bs[brow][bcol]) = b4;
        __syncthreads();

        if (k0 + BK < K) {
            a4 = *reinterpret_cast<const float4*>(Ap + k0 + BK);
            b4 = *reinterpret_cast<const float4*>(Bp + (size_t)(k0 + BK) * ldb);
        }

#pragma unroll
        for (int kk = 0; kk < BK; kk++) {
            const float4* arow = reinterpret_cast<const float4*>(&As[kk][ty * TM]);
            float4 ara = arow[0], arb = arow[1];
            u64 a2[TM];
            a2[0] = pack2(ara.x, ara.x); a2[1] = pack2(ara.y, ara.y);
            a2[2] = pack2(ara.z, ara.z); a2[3] = pack2(ara.w, ara.w);
            a2[4] = pack2(arb.x, arb.x); a2[5] = pack2(arb.y, arb.y);
            a2[6] = pack2(arb.z, arb.z); a2[7] = pack2(arb.w, arb.w);

            const u64* brow2 = reinterpret_cast<const u64*>(&Bs[kk][tx * TN]);
            u64 b2[TN / 2];
#pragma unroll
            for (int j = 0; j < TN / 2; j++) b2[j] = brow2[j];

#pragma unroll
            for (int i = 0; i < TM; i++)
#pragma unroll
                for (int j = 0; j < TN / 2; j++)
                    acc2[i][j] = ffma2(a2[i], b2[j], acc2[i][j]);
        }
        __syncthreads();
    }

    float* Cp = C + (size_t)blockIdx.y * BM * ldc;
#pragma unroll
    for (int i = 0; i < TM; i++) {
        float* crow = Cp + (size_t)(ty * TM + i) * ldc + tx * TN;
#pragma unroll
        for (int j = 0; j < TN / 2; j += 2) {
            float4 v4;
            unpack2(acc2[i][j],     v4.x, v4.y);
            unpack2(acc2[i][j + 1], v4.z, v4.w);
            *reinterpret_cast<float4*>(crow + j * 2) = v4;
        }
    }
}

// ---------------------------------------------------------------------------
// Projection kernels (x @ W^T)
// ---------------------------------------------------------------------------
__global__ __launch_bounds__(256) void k_proj_q(const float* __restrict__ x,
                                                const float* __restrict__ W) {
    gemm_core_nt(x, CDIM, W, CDIM, g_q, CDIM, CDIM, 1.0f);
}
__global__ __launch_bounds__(256) void k_proj_k(const float* __restrict__ x,
                                                const float* __restrict__ W) {
    gemm_core_nt(x, CDIM, W, CDIM, g_k, KVDIM, CDIM, 1.0f);
}
__global__ __launch_bounds__(256) void k_proj_v(const float* __restrict__ x,
                                                const float* __restrict__ W) {
    gemm_core_nt(x, CDIM, W, CDIM, g_v, KVDIM, CDIM, 1.0f);
}
__global__ __launch_bounds__(256) void k_oproj(const float* __restrict__ Wo,
                                               float* __restrict__ out) {
    gemm_core_nt(g_att, CDIM, Wo, CDIM, out, CDIM, CDIM, 1.0f);
}

// ---------------------------------------------------------------------------
// RoPE (Llama half-rotation), applied in-place to q and k.
// Tables computed in fp64 so fast-math can't hurt accuracy at ang ~ 2048 rad.
// grid = B*T blocks, 256 threads.
// ---------------------------------------------------------------------------
__global__ void k_rope(const int* __restrict__ start_pos) {
    __shared__ float cs[HDIM / 2], sn[HDIM / 2];
    const int bt  = blockIdx.x;            // b*SEQ + t
    const int t   = bt & (SEQ - 1);
    const int tid = threadIdx.x;

    if (tid < HDIM / 2) {
        double inv = pow(10000.0, -(double)(2 * tid) / (double)HDIM);
        double ang = (double)(t + start_pos[0]) * inv;
        cs[tid] = (float)cos(ang);
        sn[tid] = (float)sin(ang);
    }
    __syncthreads();

    float* qrow = g_q + (size_t)bt * CDIM;
    for (int idx = tid; idx < NHEAD * (HDIM / 2); idx += blockDim.x) {
        int h = idx >> 6, i = idx & 63;
        float x1 = qrow[h * HDIM + i];
        float x2 = qrow[h * HDIM + i + 64];
        qrow[h * HDIM + i]      = x1 * cs[i] - x2 * sn[i];
        qrow[h * HDIM + i + 64] = x2 * cs[i] + x1 * sn[i];
    }
    float* krow = g_k + (size_t)bt * KVDIM;
    for (int idx = tid; idx < NKV * (HDIM / 2); idx += blockDim.x) {
        int h = idx >> 6, i = idx & 63;
        float x1 = krow[h * HDIM + i];
        float x2 = krow[h * HDIM + i + 64];
        krow[h * HDIM + i]      = x1 * cs[i] - x2 * sn[i];
        krow[h * HDIM + i + 64] = x2 * cs[i] + x1 * sn[i];
    }
}

// ---------------------------------------------------------------------------
// Scores: S[z][s][t] = scale * q_h[s,:] . k_g[t,:]   (z = b*16 + h, g = h/4)
// grid (16, 16, 32)
// ---------------------------------------------------------------------------
__global__ __launch_bounds__(256) void k_qk() {
    const int z = blockIdx.z;
    const int b = z >> 4;
    const int h = z & 15;
    const int g = h >> 2;
    const float* A = g_q + (size_t)b * SEQ * CDIM + (size_t)h * HDIM;
    const float* B = g_k + (size_t)b * SEQ * KVDIM + (size_t)g * HDIM;
    float* C = g_s + (size_t)z * SEQ * SEQ;
    gemm_core_nt(A, CDIM, B, KVDIM, C, SEQ, HDIM, 0.08838834764831845f); // 1/sqrt(128)
}

// ---------------------------------------------------------------------------
// Row softmax over S (rows of length SEQ=2048). Warp-per-row, values held in
// registers (64/lane): 1 read + 1 write of the 537 MB buffer.
// grid = (B*NHEAD*SEQ)/8 blocks, 256 threads (8 warps).
// ---------------------------------------------------------------------------
__global__ __launch_bounds__(256) void k_softmax() {
    const int row  = blockIdx.x * 8 + (threadIdx.x >> 5);
    const int lane = threadIdx.x & 31;
    float* p = g_s + (size_t)row * SEQ;

    float vals[64];
    float m = -INFINITY;
#pragma unroll
    for (int i = 0; i < 64; i++) {
        vals[i] = p[lane + i * 32];
        m = fmaxf(m, vals[i]);
    }
#pragma unroll
    for (int o = 16; o > 0; o >>= 1) m = fmaxf(m, __shfl_xor_sync(0xFFFFFFFFu, m, o));

    float s = 0.0f;
#pragma unroll
    for (int i = 0; i < 64; i++) {
        vals[i] = expf(vals[i] - m);
        s += vals[i];
    }
#pragma unroll
    for (int o = 16; o > 0; o >>= 1) s += __shfl_xor_sync(0xFFFFFFFFu, s, o);

    const float inv = 1.0f / s;
#pragma unroll
    for (int i = 0; i < 64; i++) p[lane + i * 32] = vals[i] * inv;
}

// ---------------------------------------------------------------------------
// O_h = P @ V_g : per (b,h), [SEQ x SEQ] @ [SEQ x 128] -> g_att at head slot h
// grid (1, 16, 32)
// ---------------------------------------------------------------------------
__global__ __launch_bounds__(256) void k_pv() {
    const int z = blockIdx.z;
    const int b = z >> 4;
    const int h = z & 15;
    const int g = h >> 2;
    const float* A = g_s + (size_t)z * SEQ * SEQ;
    const float* B = g_v + (size_t)b * SEQ * KVDIM + (size_t)g * HDIM;
    float* C = g_att + (size_t)b * SEQ * CDIM + (size_t)h * HDIM;
    gemm_core_nn(A, SEQ, B, KVDIM, C, CDIM, SEQ);
}

// ---------------------------------------------------------------------------
// Entry point
// ---------------------------------------------------------------------------
extern "C" void kernel_launch(void* const* d_in, const int* in_sizes, int n_in,
                              void* d_out, int out_size) {
    const float* x  = (const float*)d_in[0];
    const float* Wq = (const float*)d_in[1];
    const float* Wk = (const float*)d_in[2];
    const float* Wv = (const float*)d_in[3];
    const float* Wo = (const float*)d_in[4];
    const int*   sp = (const int*)d_in[5];
    float* out = (float*)d_out;

    // QKV projections
    k_proj_q<<<dim3(CDIM / BN, MROWS / BM), 256>>>(x, Wq);   // (16, 32)
    k_proj_k<<<dim3(KVDIM / BN, MROWS / BM), 256>>>(x, Wk);  // (4, 32)
    k_proj_v<<<dim3(KVDIM / BN, MROWS / BM), 256>>>(x, Wv);  // (4, 32)

    // RoPE on q and k
    k_rope<<<MROWS, 256>>>(sp);

    // Attention: scores -> softmax -> PV
    k_qk<<<dim3(SEQ / BN, SEQ / BM, BATCH * NHEAD), 256>>>();
    k_softmax<<<(BATCH * NHEAD * SEQ) / 8, 256>>>();
    k_pv<<<dim3(1, SEQ / BM, BATCH * NHEAD), 256>>>();

    // Output projection
    k_oproj<<<dim3(CDIM / BN, MROWS / BM), 256>>>(Wo, out);
}

// round 5
// speedup vs baseline: 1.3126x; 1.3126x over previous
#include <cuda_runtime.h>
#include <math.h>
#include <stdint.h>

// Problem constants (fixed shapes for this problem instance)
#define BATCH   2
#define SEQ     2048
#define CDIM    2048
#define NHEAD   16
#define NKV     4
#define HDIM    128
#define MROWS   (BATCH * SEQ)          // 4096
#define KVDIM   (NKV * HDIM)           // 512

// GEMM tiling: 128x128 block tile, BK=16, 256 threads = 8 warps (2x4),
// warp tile 64x32 = 4x4 grid of m16n8k8 tf32 MMA tiles.
#define BM 128
#define BN 128
#define BK 16
#define BKP 20        // A / NT-B smem row stride ([row][k], pad 4 -> conflict-free frag gather)
#define BNP 136       // NN-B smem row stride ([k][n], pad 8 -> conflict-free frag gather)

// ---------------------------------------------------------------------------
// Static device scratch (allocation-free rule: __device__ globals)
// ---------------------------------------------------------------------------
__device__ float g_q[(size_t)MROWS * CDIM];              // 32 MB
__device__ float g_k[(size_t)MROWS * KVDIM];             // 8 MB
__device__ float g_v[(size_t)MROWS * KVDIM];             // 8 MB
__device__ float g_s[(size_t)BATCH * NHEAD * SEQ * SEQ]; // 537 MB scores
__device__ float g_att[(size_t)MROWS * CDIM];            // 32 MB

// ---------------------------------------------------------------------------
// tf32 helpers
// ---------------------------------------------------------------------------
__device__ __forceinline__ float tf32r(float x) {
    uint32_t r;
    asm("cvt.rna.tf32.f32 %0, %1;" : "=r"(r) : "f"(x));
    return __uint_as_float(r);
}

// One m16n8k8 tf32 MMA, D += A*B (row.col).
__device__ __forceinline__ void mma8(float* d, const uint32_t* a, const uint32_t* b) {
    asm("mma.sync.aligned.m16n8k8.row.col.f32.tf32.tf32.f32 "
        "{%0,%1,%2,%3}, {%4,%5,%6,%7}, {%8,%9}, {%0,%1,%2,%3};"
        : "+f"(d[0]), "+f"(d[1]), "+f"(d[2]), "+f"(d[3])
        : "r"(a[0]), "r"(a[1]), "r"(a[2]), "r"(a[3]), "r"(b[0]), "r"(b[1]));
}

// Split a float4 into tf32 hi + tf32 residual, store both planes (contiguous 16B).
__device__ __forceinline__ void split_store(float* big, float* res, float4 v) {
    float b0 = tf32r(v.x), b1 = tf32r(v.y), b2 = tf32r(v.z), b3 = tf32r(v.w);
    *reinterpret_cast<float4*>(big) = make_float4(b0, b1, b2, b3);
    *reinterpret_cast<float4*>(res) =
        make_float4(tf32r(v.x - b0), tf32r(v.y - b1), tf32r(v.z - b2), tf32r(v.w - b3));
}

// ---------------------------------------------------------------------------
// 3xTF32 GEMM core.
// TRANS_B = true : C[BM,BN] = alpha * A[BM,K] * B[BN,K]^T   (NT; both K-contig)
// TRANS_B = false: C[BM,BN] = alpha * A[BM,K] * B[K,BN]     (NN)
// Requires M%BM==0, N%BN==0, K%BK==0, pointers/ld 4-float aligned.
// ---------------------------------------------------------------------------
template<bool TRANS_B>
__device__ __forceinline__ void gemm_tf32(
    const float* __restrict__ A, int lda,
    const float* __restrict__ B, int ldb,
    float* __restrict__ C, int ldc,
    int K, float alpha)
{
    __shared__ float As[2][BM][BKP];          // [split][m][k]
    __shared__ float Bs[2 * BN * BKP];        // NT: [split][n][k] s20; NN: [split][k][n] s136
    const int NT_PLANE = BN * BKP;            // 2560 floats
    const int NN_PLANE = BK * BNP;            // 2176 floats

    const int tid  = threadIdx.x;
    const int lane = tid & 31;
    const int warp = tid >> 5;
    const int gid  = lane >> 2;     // 0..7
    const int tig  = lane & 3;      // 0..3
    const int wm   = (warp & 1) * 64;
    const int wn   = (warp >> 1) * 32;

    const float* Ab = A + (size_t)blockIdx.y * BM * lda;
    const float* Bb = TRANS_B ? (B + (size_t)blockIdx.x * BN * ldb)
                              : (B + blockIdx.x * BN);

    // loader coords
    const int ar0 = tid >> 2;             // 0..63 (and +64)
    const int ac0 = (tid & 3) << 2;       // 0,4,8,12
    const int nr0 = tid >> 5;             // NN: k-row 0..7 (and +8)
    const int nc0 = (tid & 31) << 2;      // NN: n col 0..124

    float acc[4][4][4];
#pragma unroll
    for (int i = 0; i < 4; i++)
#pragma unroll
        for (int j = 0; j < 4; j++)
#pragma unroll
            for (int r = 0; r < 4; r++) acc[i][j][r] = 0.0f;

    // initial gmem prefetch (k0 = 0)
    float4 pa0 = *reinterpret_cast<const float4*>(Ab + (size_t)ar0 * lda + ac0);
    float4 pa1 = *reinterpret_cast<const float4*>(Ab + (size_t)(ar0 + 64) * lda + ac0);
    float4 pb0, pb1;
    if (TRANS_B) {
        pb0 = *reinterpret_cast<const float4*>(Bb + (size_t)ar0 * ldb + ac0);
        pb1 = *reinterpret_cast<const float4*>(Bb + (size_t)(ar0 + 64) * ldb + ac0);
    } else {
        pb0 = *reinterpret_cast<const float4*>(Bb + (size_t)nr0 * ldb + nc0);
        pb1 = *reinterpret_cast<const float4*>(Bb + (size_t)(nr0 + 8) * ldb + nc0);
    }

    for (int k0 = 0; k0 < K; k0 += BK) {
        // stage current tile into smem (with tf32 hi/lo split)
        split_store(&As[0][ar0][ac0],      &As[1][ar0][ac0],      pa0);
        split_store(&As[0][ar0 + 64][ac0], &As[1][ar0 + 64][ac0], pa1);
        if (TRANS_B) {
            split_store(&Bs[ar0 * BKP + ac0],            &Bs[NT_PLANE + ar0 * BKP + ac0],            pb0);
            split_store(&Bs[(ar0 + 64) * BKP + ac0],     &Bs[NT_PLANE + (ar0 + 64) * BKP + ac0],     pb1);
        } else {
            split_store(&Bs[nr0 * BNP + nc0],            &Bs[NN_PLANE + nr0 * BNP + nc0],            pb0);
            split_store(&Bs[(nr0 + 8) * BNP + nc0],      &Bs[NN_PLANE + (nr0 + 8) * BNP + nc0],      pb1);
        }
        __syncthreads();

        // prefetch next tile
        if (k0 + BK < K) {
            pa0 = *reinterpret_cast<const float4*>(Ab + (size_t)ar0 * lda + k0 + BK + ac0);
            pa1 = *reinterpret_cast<const float4*>(Ab + (size_t)(ar0 + 64) * lda + k0 + BK + ac0);
            if (TRANS_B) {
                pb0 = *reinterpret_cast<const float4*>(Bb + (size_t)ar0 * ldb + k0 + BK + ac0);
                pb1 = *reinterpret_cast<const float4*>(Bb + (size_t)(ar0 + 64) * ldb + k0 + BK + ac0);
            } else {
                pb0 = *reinterpret_cast<const float4*>(Bb + (size_t)(k0 + BK + nr0) * ldb + nc0);
                pb1 = *reinterpret_cast<const float4*>(Bb + (size_t)(k0 + BK + nr0 + 8) * ldb + nc0);
            }
        }

        // compute: two k8 substeps per BK=16
#pragma unroll
        for (int ks = 0; ks < 2; ks++) {
            const int kk = ks * 8;
            // B fragments (hi + residual)
            uint32_t bb[4][2], brr[4][2];
#pragma unroll
            for (int nt = 0; nt < 4; nt++) {
                const int n = wn + nt * 8 + gid;
                if (TRANS_B) {
                    bb[nt][0]  = __float_as_uint(Bs[n * BKP + kk + tig]);
                    bb[nt][1]  = __float_as_uint(Bs[n * BKP + kk + tig + 4]);
                    brr[nt][0] = __float_as_uint(Bs[NT_PLANE + n * BKP + kk + tig]);
                    brr[nt][1] = __float_as_uint(Bs[NT_PLANE + n * BKP + kk + tig + 4]);
                } else {
                    bb[nt][0]  = __float_as_uint(Bs[(kk + tig) * BNP + n]);
                    bb[nt][1]  = __float_as_uint(Bs[(kk + tig + 4) * BNP + n]);
                    brr[nt][0] = __float_as_uint(Bs[NN_PLANE + (kk + tig) * BNP + n]);
                    brr[nt][1] = __float_as_uint(Bs[NN_PLANE + (kk + tig + 4) * BNP + n]);
                }
            }
            // A fragments per m-tile, then 3xTF32 MMAs
#pragma unroll
            for (int mt = 0; mt < 4; mt++) {
                const int m = wm + mt * 16 + gid;
                uint32_t ab[4], ar[4];
                ab[0] = __float_as_uint(As[0][m][kk + tig]);
                ab[1] = __float_as_uint(As[0][m + 8][kk + tig]);
                ab[2] = __float_as_uint(As[0][m][kk + tig + 4]);
                ab[3] = __float_as_uint(As[0][m + 8][kk + tig + 4]);
                ar[0] = __float_as_uint(As[1][m][kk + tig]);
                ar[1] = __float_as_uint(As[1][m + 8][kk + tig]);
                ar[2] = __float_as_uint(As[1][m][kk + tig + 4]);
                ar[3] = __float_as_uint(As[1][m + 8][kk + tig + 4]);
#pragma unroll
                for (int nt = 0; nt < 4; nt++) {
                    mma8(acc[mt][nt], ab, bb[nt]);   // hi * hi
                    mma8(acc[mt][nt], ab, brr[nt]);  // hi * lo
                    mma8(acc[mt][nt], ar, bb[nt]);   // lo * hi
                }
            }
        }
        __syncthreads();
    }

    // epilogue: d fragment layout c0:(g, 2t) c1:(g, 2t+1) c2:(g+8, 2t) c3:(g+8, 2t+1)
    float* Cb = C + (size_t)blockIdx.y * BM * ldc + (size_t)blockIdx.x * BN;
#pragma unroll
    for (int mt = 0; mt < 4; mt++) {
        const int row = wm + mt * 16 + gid;
#pragma unroll
        for (int nt = 0; nt < 4; nt++) {
            const int col = wn + nt * 8 + 2 * tig;
            float* c0 = Cb + (size_t)row * ldc + col;
            float* c1 = Cb + (size_t)(row + 8) * ldc + col;
            *reinterpret_cast<float2*>(c0) =
                make_float2(acc[mt][nt][0] * alpha, acc[mt][nt][1] * alpha);
            *reinterpret_cast<float2*>(c1) =
                make_float2(acc[mt][nt][2] * alpha, acc[mt][nt][3] * alpha);
        }
    }
}

// ---------------------------------------------------------------------------
// Projection kernels (x @ W^T)
// ---------------------------------------------------------------------------
__global__ __launch_bounds__(256) void k_proj_q(const float* __restrict__ x,
                                                const float* __restrict__ W) {
    gemm_tf32<true>(x, CDIM, W, CDIM, g_q, CDIM, CDIM, 1.0f);
}
__global__ __launch_bounds__(256) void k_proj_k(const float* __restrict__ x,
                                                const float* __restrict__ W) {
    gemm_tf32<true>(x, CDIM, W, CDIM, g_k, KVDIM, CDIM, 1.0f);
}
__global__ __launch_bounds__(256) void k_proj_v(const float* __restrict__ x,
                                                const float* __restrict__ W) {
    gemm_tf32<true>(x, CDIM, W, CDIM, g_v, KVDIM, CDIM, 1.0f);
}
__global__ __launch_bounds__(256) void k_oproj(const float* __restrict__ Wo,
                                               float* __restrict__ out) {
    gemm_tf32<true>(g_att, CDIM, Wo, CDIM, out, CDIM, CDIM, 1.0f);
}

// ---------------------------------------------------------------------------
// RoPE (Llama half-rotation), in-place on q and k; fp64 tables.
// ---------------------------------------------------------------------------
__global__ void k_rope(const int* __restrict__ start_pos) {
    __shared__ float cs[HDIM / 2], sn[HDIM / 2];
    const int bt  = blockIdx.x;
    const int t   = bt & (SEQ - 1);
    const int tid = threadIdx.x;

    if (tid < HDIM / 2) {
        double inv = pow(10000.0, -(double)(2 * tid) / (double)HDIM);
        double ang = (double)(t + start_pos[0]) * inv;
        cs[tid] = (float)cos(ang);
        sn[tid] = (float)sin(ang);
    }
    __syncthreads();

    float* qrow = g_q + (size_t)bt * CDIM;
    for (int idx = tid; idx < NHEAD * (HDIM / 2); idx += blockDim.x) {
        int h = idx >> 6, i = idx & 63;
        float x1 = qrow[h * HDIM + i];
        float x2 = qrow[h * HDIM + i + 64];
        qrow[h * HDIM + i]      = x1 * cs[i] - x2 * sn[i];
        qrow[h * HDIM + i + 64] = x2 * cs[i] + x1 * sn[i];
    }
    float* krow = g_k + (size_t)bt * KVDIM;
    for (int idx = tid; idx < NKV * (HDIM / 2); idx += blockDim.x) {
        int h = idx >> 6, i = idx & 63;
        float x1 = krow[h * HDIM + i];
        float x2 = krow[h * HDIM + i + 64];
        krow[h * HDIM + i]      = x1 * cs[i] - x2 * sn[i];
        krow[h * HDIM + i + 64] = x2 * cs[i] + x1 * sn[i];
    }
}

// ---------------------------------------------------------------------------
// Scores: S[z][s][t] = scale * q_h[s,:] . k_g[t,:]   (z = b*16 + h, g = h/4)
// ---------------------------------------------------------------------------
__global__ __launch_bounds__(256) void k_qk() {
    const int z = blockIdx.z;
    const int b = z >> 4;
    const int h = z & 15;
    const int g = h >> 2;
    const float* A = g_q + (size_t)b * SEQ * CDIM + (size_t)h * HDIM;
    const float* B = g_k + (size_t)b * SEQ * KVDIM + (size_t)g * HDIM;
    float* C = g_s + (size_t)z * SEQ * SEQ;
    gemm_tf32<true>(A, CDIM, B, KVDIM, C, SEQ, HDIM, 0.08838834764831845f);
}

// ---------------------------------------------------------------------------
// Row softmax over S (rows of length SEQ). Warp-per-row, register-resident.
// ---------------------------------------------------------------------------
__global__ __launch_bounds__(256) void k_softmax() {
    const int row  = blockIdx.x * 8 + (threadIdx.x >> 5);
    const int lane = threadIdx.x & 31;
    float* p = g_s + (size_t)row * SEQ;

    float vals[64];
    float m = -INFINITY;
#pragma unroll
    for (int i = 0; i < 64; i++) {
        vals[i] = p[lane + i * 32];
        m = fmaxf(m, vals[i]);
    }
#pragma unroll
    for (int o = 16; o > 0; o >>= 1) m = fmaxf(m, __shfl_xor_sync(0xFFFFFFFFu, m, o));

    float s = 0.0f;
#pragma unroll
    for (int i = 0; i < 64; i++) {
        vals[i] = expf(vals[i] - m);
        s += vals[i];
    }
#pragma unroll
    for (int o = 16; o > 0; o >>= 1) s += __shfl_xor_sync(0xFFFFFFFFu, s, o);

    const float inv = 1.0f / s;
#pragma unroll
    for (int i = 0; i < 64; i++) p[lane + i * 32] = vals[i] * inv;
}

// ---------------------------------------------------------------------------
// O_h = P @ V_g : per (b,h), [SEQ x SEQ] @ [SEQ x 128] -> g_att head slot h
// ---------------------------------------------------------------------------
__global__ __launch_bounds__(256) void k_pv() {
    const int z = blockIdx.z;
    const int b = z >> 4;
    const int h = z & 15;
    const int g = h >> 2;
    const float* A = g_s + (size_t)z * SEQ * SEQ;
    const float* B = g_v + (size_t)b * SEQ * KVDIM + (size_t)g * HDIM;
    float* C = g_att + (size_t)b * SEQ * CDIM + (size_t)h * HDIM;
    gemm_tf32<false>(A, SEQ, B, KVDIM, C, CDIM, SEQ, 1.0f);
}

// ---------------------------------------------------------------------------
// Entry point
// ---------------------------------------------------------------------------
extern "C" void kernel_launch(void* const* d_in, const int* in_sizes, int n_in,
                              void* d_out, int out_size) {
    const float* x  = (const float*)d_in[0];
    const float* Wq = (const float*)d_in[1];
    const float* Wk = (const float*)d_in[2];
    const float* Wv = (const float*)d_in[3];
    const float* Wo = (const float*)d_in[4];
    const int*   sp = (const int*)d_in[5];
    float* out = (float*)d_out;

    k_proj_q<<<dim3(CDIM / BN, MROWS / BM), 256>>>(x, Wq);
    k_proj_k<<<dim3(KVDIM / BN, MROWS / BM), 256>>>(x, Wk);
    k_proj_v<<<dim3(KVDIM / BN, MROWS / BM), 256>>>(x, Wv);

    k_rope<<<MROWS, 256>>>(sp);

    k_qk<<<dim3(SEQ / BN, SEQ / BM, BATCH * NHEAD), 256>>>();
    k_softmax<<<(BATCH * NHEAD * SEQ) / 8, 256>>>();
    k_pv<<<dim3(1, SEQ / BM, BATCH * NHEAD), 256>>>();

    k_oproj<<<dim3(CDIM / BN, MROWS / BM), 256>>>(Wo, out);
}

// round 8
// speedup vs baseline: 1.9140x; 1.4582x over previous
#include <cuda_runtime.h>
#include <cuda_fp16.h>
#include <math.h>
#include <stdint.h>

// Problem constants
#define BATCH   2
#define SEQ     2048
#define CDIM    2048
#define NHEAD   16
#define NKV     4
#define HDIM    128
#define MROWS   (BATCH * SEQ)          // 4096
#define KVDIM   (NKV * HDIM)           // 512

// GEMM tiling: 128x128 CTA tile, BK=32 fp32 k-elements per stage,
// 8 warps (2x4), warp tile 64x32 = 4x4 m16n8k16 fp16 MMAs, 3-term split.
#define BM 128
#define BN 128
#define BK 32
#define RS 20                  // 32-bit words per smem row (16 data words + 4 pad)
#define PLANE_W (128 * RS)     // words per plane
#define PLANE_B (PLANE_W * 4)  // bytes per plane (10240)
#define NTHREADS 256

// ---------------------------------------------------------------------------
// Static device scratch
// ---------------------------------------------------------------------------
__device__ float g_q[(size_t)MROWS * CDIM];              // 32 MB
__device__ float g_k[(size_t)MROWS * KVDIM];             // 8 MB
__device__ float g_v[(size_t)MROWS * KVDIM];             // 8 MB
__device__ float g_vt[(size_t)BATCH * KVDIM * SEQ];      // 8 MB  V^T per batch
__device__ float g_s[(size_t)BATCH * NHEAD * SEQ * SEQ]; // 537 MB scores
__device__ float g_att[(size_t)MROWS * CDIM];            // 32 MB

// ---------------------------------------------------------------------------
// Helpers
// ---------------------------------------------------------------------------
__device__ __forceinline__ uint32_t s2u(const void* p) {
    uint32_t a;
    asm("{ .reg .u64 t; cvta.to.shared.u64 t, %1; cvt.u32.u64 %0, t; }" : "=r"(a) : "l"(p));
    return a;
}
// fp16 2-way split of a float pair -> packed hi word + residual word.
__device__ __forceinline__ void split2(float x, float y, uint32_t& hw, uint32_t& lw) {
    __half2 h = __floats2half2_rn(x, y);
    float2 hf = __half22float2(h);
    __half2 l = __floats2half2_rn(x - hf.x, y - hf.y);
    hw = *reinterpret_cast<uint32_t*>(&h);
    lw = *reinterpret_cast<uint32_t*>(&l);
}
__device__ __forceinline__ void ldsm4(uint32_t addr, uint32_t& r0, uint32_t& r1,
                                      uint32_t& r2, uint32_t& r3) {
    asm volatile("ldmatrix.sync.aligned.m8n8.x4.shared.b16 {%0,%1,%2,%3}, [%4];"
                 : "=r"(r0), "=r"(r1), "=r"(r2), "=r"(r3) : "r"(addr));
}
__device__ __forceinline__ void mma16(float* d, uint32_t a0, uint32_t a1, uint32_t a2,
                                      uint32_t a3, uint32_t b0, uint32_t b1) {
    asm volatile(
        "mma.sync.aligned.m16n8k16.row.col.f32.f16.f16.f32 "
        "{%0,%1,%2,%3}, {%4,%5,%6,%7}, {%8,%9}, {%0,%1,%2,%3};"
        : "+f"(d[0]), "+f"(d[1]), "+f"(d[2]), "+f"(d[3])
        : "r"(a0), "r"(a1), "r"(a2), "r"(a3), "r"(b0), "r"(b1));
}

// ---------------------------------------------------------------------------
// NT GEMM core: C[BM,BN] = alpha * A[BM,K] * B[BN,K]^T, 3-term fp16 split.
// Requires M%128==0, N%128==0, K%32==0, rows 16B-aligned.
// ---------------------------------------------------------------------------
__device__ void gemm_fp16_nt(const float* __restrict__ A, int lda,
                             const float* __restrict__ B, int ldb,
                             float* __restrict__ C, int ldc,
                             int K, float alpha)
{
    __shared__ uint32_t sm[4][PLANE_W];      // Ah, Al, Bh, Bl  (40 KB)
    uint32_t* sAh = sm[0];
    uint32_t* sAl = sm[1];
    uint32_t* sBh = sm[2];
    uint32_t* sBl = sm[3];
    const uint32_t ub = s2u(sm);             // byte address of Ah plane

    const int tid  = threadIdx.x;
    const int lane = tid & 31;
    const int warp = tid >> 5;
    const int gid  = lane >> 2;
    const int tig  = lane & 3;
    const int wm   = (warp & 1) * 64;
    const int wn   = (warp >> 1) * 32;

    // loader: thread t -> row r = t/2, 16 floats at col (t&1)*16
    const int r  = tid >> 1;
    const int ch = tid & 1;
    const float* Ap = A + (size_t)(blockIdx.y * BM + r) * lda + ch * 16;
    const float* Bp = B + (size_t)(blockIdx.x * BN + r) * ldb + ch * 16;

    float acc[4][4][4];
#pragma unroll
    for (int i = 0; i < 4; i++)
#pragma unroll
        for (int j = 0; j < 4; j++)
#pragma unroll
            for (int q = 0; q < 4; q++) acc[i][j][q] = 0.0f;

    float4 pa[4], pb[4];
#pragma unroll
    for (int i = 0; i < 4; i++) {
        pa[i] = *reinterpret_cast<const float4*>(Ap + 4 * i);
        pb[i] = *reinterpret_cast<const float4*>(Bp + 4 * i);
    }

    const int wo = r * RS + ch * 8;   // word offset for this thread's 8 data words

    for (int kc = 0; kc < K; kc += BK) {
        // stage current tile (fp16 hi/lo split)
        {
            uint32_t hw[8], lw[8];
#pragma unroll
            for (int i = 0; i < 4; i++) {
                split2(pa[i].x, pa[i].y, hw[2 * i],     lw[2 * i]);
                split2(pa[i].z, pa[i].w, hw[2 * i + 1], lw[2 * i + 1]);
            }
            *reinterpret_cast<uint4*>(&sAh[wo])     = make_uint4(hw[0], hw[1], hw[2], hw[3]);
            *reinterpret_cast<uint4*>(&sAh[wo + 4]) = make_uint4(hw[4], hw[5], hw[6], hw[7]);
            *reinterpret_cast<uint4*>(&sAl[wo])     = make_uint4(lw[0], lw[1], lw[2], lw[3]);
            *reinterpret_cast<uint4*>(&sAl[wo + 4]) = make_uint4(lw[4], lw[5], lw[6], lw[7]);
#pragma unroll
            for (int i = 0; i < 4; i++) {
                split2(pb[i].x, pb[i].y, hw[2 * i],     lw[2 * i]);
                split2(pb[i].z, pb[i].w, hw[2 * i + 1], lw[2 * i + 1]);
            }
            *reinterpret_cast<uint4*>(&sBh[wo])     = make_uint4(hw[0], hw[1], hw[2], hw[3]);
            *reinterpret_cast<uint4*>(&sBh[wo + 4]) = make_uint4(hw[4], hw[5], hw[6], hw[7]);
            *reinterpret_cast<uint4*>(&sBl[wo])     = make_uint4(lw[0], lw[1], lw[2], lw[3]);
            *reinterpret_cast<uint4*>(&sBl[wo + 4]) = make_uint4(lw[4], lw[5], lw[6], lw[7]);
        }
        __syncthreads();

        // prefetch next tile
        if (kc + BK < K) {
#pragma unroll
            for (int i = 0; i < 4; i++) {
                pa[i] = *reinterpret_cast<const float4*>(Ap + kc + BK + 4 * i);
                pb[i] = *reinterpret_cast<const float4*>(Bp + kc + BK + 4 * i);
            }
        }

        // compute: two k16 substeps
#pragma unroll
        for (int ks = 0; ks < 2; ks++) {
            const int kw = ks * 8;   // word offset of this substep's 16 values

            // B fragments (hi + lo), scalar conflict-free LDS
            uint32_t bh[4][2], bl[4][2];
#pragma unroll
            for (int nt = 0; nt < 4; nt++) {
                const int bidx = (wn + nt * 8 + gid) * RS + kw + tig;
                bh[nt][0] = sBh[bidx];
                bh[nt][1] = sBh[bidx + 4];
                bl[nt][0] = sBl[bidx];
                bl[nt][1] = sBl[bidx + 4];
            }

            // A fragments via ldmatrix.x4, then 3-term MMAs
#pragma unroll
            for (int mt = 0; mt < 4; mt++) {
                const int arow = wm + mt * 16 + (lane & 15);
                const uint32_t aoff = (uint32_t)(arow * RS + kw + (lane >> 4) * 4) * 4u;
                uint32_t ah0, ah1, ah2, ah3, al0, al1, al2, al3;
                ldsm4(ub + aoff,            ah0, ah1, ah2, ah3);
                ldsm4(ub + PLANE_B + aoff,  al0, al1, al2, al3);
#pragma unroll
                for (int nt = 0; nt < 4; nt++) {
                    mma16(acc[mt][nt], ah0, ah1, ah2, ah3, bh[nt][0], bh[nt][1]);
                    mma16(acc[mt][nt], ah0, ah1, ah2, ah3, bl[nt][0], bl[nt][1]);
                    mma16(acc[mt][nt], al0, al1, al2, al3, bh[nt][0], bh[nt][1]);
                }
            }
        }
        __syncthreads();
    }

    // epilogue: c0:(g,2t) c1:(g,2t+1) c2:(g+8,2t) c3:(g+8,2t+1)
    float* Cb = C + (size_t)blockIdx.y * BM * ldc + (size_t)blockIdx.x * BN;
#pragma unroll
    for (int mt = 0; mt < 4; mt++) {
        const int row = wm + mt * 16 + gid;
#pragma unroll
        for (int nt = 0; nt < 4; nt++) {
            const int col = wn + nt * 8 + 2 * tig;
            *reinterpret_cast<float2*>(Cb + (size_t)row * ldc + col) =
                make_float2(acc[mt][nt][0] * alpha, acc[mt][nt][1] * alpha);
            *reinterpret_cast<float2*>(Cb + (size_t)(row + 8) * ldc + col) =
                make_float2(acc[mt][nt][2] * alpha, acc[mt][nt][3] * alpha);
        }
    }
}

// ---------------------------------------------------------------------------
// GEMM wrapper kernels
// ---------------------------------------------------------------------------
__global__ __launch_bounds__(NTHREADS) void k_proj_q(const float* __restrict__ x,
                                                     const float* __restrict__ W) {
    gemm_fp16_nt(x, CDIM, W, CDIM, g_q, CDIM, CDIM, 1.0f);
}
// Fused K+V projection: blockIdx.z selects weight/output (fills the chip better).
__global__ __launch_bounds__(NTHREADS) void k_proj_kv(const float* __restrict__ x,
                                                      const float* __restrict__ Wk,
                                                      const float* __restrict__ Wv) {
    const float* W = blockIdx.z ? Wv : Wk;
    float* O = blockIdx.z ? g_v : g_k;
    gemm_fp16_nt(x, CDIM, W, CDIM, O, KVDIM, CDIM, 1.0f);
}
__global__ __launch_bounds__(NTHREADS) void k_oproj(const float* __restrict__ Wo,
                                                    float* __restrict__ out) {
    gemm_fp16_nt(g_att, CDIM, Wo, CDIM, out, CDIM, CDIM, 1.0f);
}
__global__ __launch_bounds__(NTHREADS) void k_qk() {
    const int z = blockIdx.z;
    const int b = z >> 4;
    const int h = z & 15;
    const int g = h >> 2;
    const float* A = g_q + (size_t)b * SEQ * CDIM + (size_t)h * HDIM;
    const float* B = g_k + (size_t)b * SEQ * KVDIM + (size_t)g * HDIM;
    float* C = g_s + (size_t)z * SEQ * SEQ;
    gemm_fp16_nt(A, CDIM, B, KVDIM, C, SEQ, HDIM, 0.08838834764831845f);
}
__global__ __launch_bounds__(NTHREADS) void k_pv() {
    const int z = blockIdx.z;
    const int b = z >> 4;
    const int h = z & 15;
    const int g = h >> 2;
    const float* A = g_s + (size_t)z * SEQ * SEQ;
    const float* B = g_vt + ((size_t)b * KVDIM + (size_t)g * HDIM) * SEQ;
    float* C = g_att + (size_t)b * SEQ * CDIM + (size_t)h * HDIM;
    gemm_fp16_nt(A, SEQ, B, SEQ, C, CDIM, SEQ, 1.0f);
}

// ---------------------------------------------------------------------------
// V transpose: g_vt[b][d][t] = g_v[b][t][d]
// ---------------------------------------------------------------------------
__global__ void k_vt() {
    __shared__ float tile[32][33];
    const int b  = blockIdx.z;
    const int t0 = blockIdx.x * 32;
    const int d0 = blockIdx.y * 32;
    const int tx = threadIdx.x, ty = threadIdx.y;
#pragma unroll
    for (int j = 0; j < 4; j++) {
        tile[ty + 8 * j][tx] =
            g_v[((size_t)b * SEQ + t0 + ty + 8 * j) * KVDIM + d0 + tx];
    }
    __syncthreads();
#pragma unroll
    for (int j = 0; j < 4; j++) {
        g_vt[((size_t)b * KVDIM + d0 + ty + 8 * j) * SEQ + t0 + tx] =
            tile[tx][ty + 8 * j];
    }
}

// ---------------------------------------------------------------------------
// RoPE (Llama half-rotation), in-place on q and k; fp64 tables.
// ---------------------------------------------------------------------------
__global__ void k_rope(const int* __restrict__ start_pos) {
    __shared__ float cs[HDIM / 2], sn[HDIM / 2];
    const int bt  = blockIdx.x;
    const int t   = bt & (SEQ - 1);
    const int tid = threadIdx.x;

    if (tid < HDIM / 2) {
        double inv = pow(10000.0, -(double)(2 * tid) / (double)HDIM);
        double ang = (double)(t + start_pos[0]) * inv;
        cs[tid] = (float)cos(ang);
        sn[tid] = (float)sin(ang);
    }
    __syncthreads();

    float* qrow = g_q + (size_t)bt * CDIM;
    for (int idx = tid; idx < NHEAD * (HDIM / 2); idx += blockDim.x) {
        int h = idx >> 6, i = idx & 63;
        float x1 = qrow[h * HDIM + i];
        float x2 = qrow[h * HDIM + i + 64];
        qrow[h * HDIM + i]      = x1 * cs[i] - x2 * sn[i];
        qrow[h * HDIM + i + 64] = x2 * cs[i] + x1 * sn[i];
    }
    float* krow = g_k + (size_t)bt * KVDIM;
    for (int idx = tid; idx < NKV * (HDIM / 2); idx += blockDim.x) {
        int h = idx >> 6, i = idx & 63;
        float x1 = krow[h * HDIM + i];
        float x2 = krow[h * HDIM + i + 64];
        krow[h * HDIM + i]      = x1 * cs[i] - x2 * sn[i];
        krow[h * HDIM + i + 64] = x2 * cs[i] + x1 * sn[i];
    }
}

// ---------------------------------------------------------------------------
// Row softmax over S. Warp-per-row, register-resident.
// ---------------------------------------------------------------------------
__global__ __launch_bounds__(256) void k_softmax() {
    const int row  = blockIdx.x * 8 + (threadIdx.x >> 5);
    const int lane = threadIdx.x & 31;
    float* p = g_s + (size_t)row * SEQ;

    float vals[64];
    float m = -INFINITY;
#pragma unroll
    for (int i = 0; i < 64; i++) {
        vals[i] = p[lane + i * 32];
        m = fmaxf(m, vals[i]);
    }
#pragma unroll
    for (int o = 16; o > 0; o >>= 1) m = fmaxf(m, __shfl_xor_sync(0xFFFFFFFFu, m, o));

    float s = 0.0f;
#pragma unroll
    for (int i = 0; i < 64; i++) {
        vals[i] = expf(vals[i] - m);
        s += vals[i];
    }
#pragma unroll
    for (int o = 16; o > 0; o >>= 1) s += __shfl_xor_sync(0xFFFFFFFFu, s, o);

    const float inv = 1.0f / s;
#pragma unroll
    for (int i = 0; i < 64; i++) p[lane + i * 32] = vals[i] * inv;
}

// ---------------------------------------------------------------------------
// Entry point
// ---------------------------------------------------------------------------
extern "C" void kernel_launch(void* const* d_in, const int* in_sizes, int n_in,
                              void* d_out, int out_size) {
    const float* x  = (const float*)d_in[0];
    const float* Wq = (const float*)d_in[1];
    const float* Wk = (const float*)d_in[2];
    const float* Wv = (const float*)d_in[3];
    const float* Wo = (const float*)d_in[4];
    const int*   sp = (const int*)d_in[5];
    float* out = (float*)d_out;

    k_proj_q<<<dim3(CDIM / BN, MROWS / BM), NTHREADS>>>(x, Wq);
    k_proj_kv<<<dim3(KVDIM / BN, MROWS / BM, 2), NTHREADS>>>(x, Wk, Wv);

    k_rope<<<MROWS, 256>>>(sp);
    k_vt<<<dim3(SEQ / 32, KVDIM / 32, BATCH), dim3(32, 8)>>>();

    k_qk<<<dim3(SEQ / BN, SEQ / BM, BATCH * NHEAD), NTHREADS>>>();
    k_softmax<<<(BATCH * NHEAD * SEQ) / 8, 256>>>();
    k_pv<<<dim3(1, SEQ / BM, BATCH * NHEAD), NTHREADS>>>();

    k_oproj<<<dim3(CDIM / BN, MROWS / BM), NTHREADS>>>(Wo, out);
}

// round 9
// speedup vs baseline: 1.9552x; 1.0215x over previous
#include <cuda_runtime.h>
#include <cuda_fp16.h>
#include <math.h>
#include <stdint.h>

// Problem constants
#define BATCH   2
#define SEQ     2048
#define CDIM    2048
#define NHEAD   16
#define NKV     4
#define HDIM    128
#define MROWS   (BATCH * SEQ)          // 4096
#define KVDIM   (NKV * HDIM)           // 512
#define SCALE   0.08838834764831845f   // 1/sqrt(128)

// Projection GEMM tiling (round-8 core, unchanged)
#define BM 128
#define BN 128
#define BK 32
#define RS 20
#define PLANE_W (128 * RS)
#define PLANE_B (PLANE_W * 4)
#define NTHREADS 256

// Flash kernel smem: 6 planes of [128 rows x 68 words] (64 data words = 128 halfs)
#define FW  68
#define FPL (128 * FW)                 // words per plane
#define SMEM_FLASH (6 * FPL * 4)       // 208896 bytes

// ---------------------------------------------------------------------------
// Static device scratch
// ---------------------------------------------------------------------------
__device__ float g_q[(size_t)MROWS * CDIM];              // 32 MB
__device__ float g_k[(size_t)MROWS * KVDIM];             // 8 MB
__device__ float g_v[(size_t)MROWS * KVDIM];             // 8 MB
__device__ float g_vt[(size_t)BATCH * KVDIM * SEQ];      // 8 MB  V^T per batch
__device__ float g_att[(size_t)MROWS * CDIM];            // 32 MB

// ---------------------------------------------------------------------------
// Helpers
// ---------------------------------------------------------------------------
__device__ __forceinline__ uint32_t s2u(const void* p) {
    uint32_t a;
    asm("{ .reg .u64 t; cvta.to.shared.u64 t, %1; cvt.u32.u64 %0, t; }" : "=r"(a) : "l"(p));
    return a;
}
// fp16 2-way split of a float pair -> packed hi word + residual word.
__device__ __forceinline__ void split2(float x, float y, uint32_t& hw, uint32_t& lw) {
    __half2 h = __floats2half2_rn(x, y);
    float2 hf = __half22float2(h);
    __half2 l = __floats2half2_rn(x - hf.x, y - hf.y);
    hw = *reinterpret_cast<uint32_t*>(&h);
    lw = *reinterpret_cast<uint32_t*>(&l);
}
__device__ __forceinline__ void ldsm4(uint32_t addr, uint32_t& r0, uint32_t& r1,
                                      uint32_t& r2, uint32_t& r3) {
    asm volatile("ldmatrix.sync.aligned.m8n8.x4.shared.b16 {%0,%1,%2,%3}, [%4];"
                 : "=r"(r0), "=r"(r1), "=r"(r2), "=r"(r3) : "r"(addr));
}
__device__ __forceinline__ void mma16(float* d, uint32_t a0, uint32_t a1, uint32_t a2,
                                      uint32_t a3, uint32_t b0, uint32_t b1) {
    asm volatile(
        "mma.sync.aligned.m16n8k16.row.col.f32.f16.f16.f32 "
        "{%0,%1,%2,%3}, {%4,%5,%6,%7}, {%8,%9}, {%0,%1,%2,%3};"
        : "+f"(d[0]), "+f"(d[1]), "+f"(d[2]), "+f"(d[3])
        : "r"(a0), "r"(a1), "r"(a2), "r"(a3), "r"(b0), "r"(b1));
}

// ---------------------------------------------------------------------------
// NT GEMM core (projections): C = alpha * A * B^T, 3-term fp16 split.
// ---------------------------------------------------------------------------
__device__ void gemm_fp16_nt(const float* __restrict__ A, int lda,
                             const float* __restrict__ B, int ldb,
                             float* __restrict__ C, int ldc,
                             int K, float alpha)
{
    __shared__ uint32_t sm[4][PLANE_W];
    uint32_t* sAh = sm[0];
    uint32_t* sAl = sm[1];
    uint32_t* sBh = sm[2];
    uint32_t* sBl = sm[3];
    const uint32_t ub = s2u(sm);

    const int tid  = threadIdx.x;
    const int lane = tid & 31;
    const int warp = tid >> 5;
    const int gid  = lane >> 2;
    const int tig  = lane & 3;
    const int wm   = (warp & 1) * 64;
    const int wn   = (warp >> 1) * 32;

    const int r  = tid >> 1;
    const int ch = tid & 1;
    const float* Ap = A + (size_t)(blockIdx.y * BM + r) * lda + ch * 16;
    const float* Bp = B + (size_t)(blockIdx.x * BN + r) * ldb + ch * 16;

    float acc[4][4][4];
#pragma unroll
    for (int i = 0; i < 4; i++)
#pragma unroll
        for (int j = 0; j < 4; j++)
#pragma unroll
            for (int q = 0; q < 4; q++) acc[i][j][q] = 0.0f;

    float4 pa[4], pb[4];
#pragma unroll
    for (int i = 0; i < 4; i++) {
        pa[i] = *reinterpret_cast<const float4*>(Ap + 4 * i);
        pb[i] = *reinterpret_cast<const float4*>(Bp + 4 * i);
    }

    const int wo = r * RS + ch * 8;

    for (int kc = 0; kc < K; kc += BK) {
        {
            uint32_t hw[8], lw[8];
#pragma unroll
            for (int i = 0; i < 4; i++) {
                split2(pa[i].x, pa[i].y, hw[2 * i],     lw[2 * i]);
                split2(pa[i].z, pa[i].w, hw[2 * i + 1], lw[2 * i + 1]);
            }
            *reinterpret_cast<uint4*>(&sAh[wo])     = make_uint4(hw[0], hw[1], hw[2], hw[3]);
            *reinterpret_cast<uint4*>(&sAh[wo + 4]) = make_uint4(hw[4], hw[5], hw[6], hw[7]);
            *reinterpret_cast<uint4*>(&sAl[wo])     = make_uint4(lw[0], lw[1], lw[2], lw[3]);
            *reinterpret_cast<uint4*>(&sAl[wo + 4]) = make_uint4(lw[4], lw[5], lw[6], lw[7]);
#pragma unroll
            for (int i = 0; i < 4; i++) {
                split2(pb[i].x, pb[i].y, hw[2 * i],     lw[2 * i]);
                split2(pb[i].z, pb[i].w, hw[2 * i + 1], lw[2 * i + 1]);
            }
            *reinterpret_cast<uint4*>(&sBh[wo])     = make_uint4(hw[0], hw[1], hw[2], hw[3]);
            *reinterpret_cast<uint4*>(&sBh[wo + 4]) = make_uint4(hw[4], hw[5], hw[6], hw[7]);
            *reinterpret_cast<uint4*>(&sBl[wo])     = make_uint4(lw[0], lw[1], lw[2], lw[3]);
            *reinterpret_cast<uint4*>(&sBl[wo + 4]) = make_uint4(lw[4], lw[5], lw[6], lw[7]);
        }
        __syncthreads();

        if (kc + BK < K) {
#pragma unroll
            for (int i = 0; i < 4; i++) {
                pa[i] = *reinterpret_cast<const float4*>(Ap + kc + BK + 4 * i);
                pb[i] = *reinterpret_cast<const float4*>(Bp + kc + BK + 4 * i);
            }
        }

#pragma unroll
        for (int ks = 0; ks < 2; ks++) {
            const int kw = ks * 8;
            uint32_t bh[4][2], bl[4][2];
#pragma unroll
            for (int nt = 0; nt < 4; nt++) {
                const int bidx = (wn + nt * 8 + gid) * RS + kw + tig;
                bh[nt][0] = sBh[bidx];
                bh[nt][1] = sBh[bidx + 4];
                bl[nt][0] = sBl[bidx];
                bl[nt][1] = sBl[bidx + 4];
            }
#pragma unroll
            for (int mt = 0; mt < 4; mt++) {
                const int arow = wm + mt * 16 + (lane & 15);
                const uint32_t aoff = (uint32_t)(arow * RS + kw + (lane >> 4) * 4) * 4u;
                uint32_t ah0, ah1, ah2, ah3, al0, al1, al2, al3;
                ldsm4(ub + aoff,            ah0, ah1, ah2, ah3);
                ldsm4(ub + PLANE_B + aoff,  al0, al1, al2, al3);
#pragma unroll
                for (int nt = 0; nt < 4; nt++) {
                    mma16(acc[mt][nt], ah0, ah1, ah2, ah3, bh[nt][0], bh[nt][1]);
                    mma16(acc[mt][nt], ah0, ah1, ah2, ah3, bl[nt][0], bl[nt][1]);
                    mma16(acc[mt][nt], al0, al1, al2, al3, bh[nt][0], bh[nt][1]);
                }
            }
        }
        __syncthreads();
    }

    float* Cb = C + (size_t)blockIdx.y * BM * ldc + (size_t)blockIdx.x * BN;
#pragma unroll
    for (int mt = 0; mt < 4; mt++) {
        const int row = wm + mt * 16 + gid;
#pragma unroll
        for (int nt = 0; nt < 4; nt++) {
            const int col = wn + nt * 8 + 2 * tig;
            *reinterpret_cast<float2*>(Cb + (size_t)row * ldc + col) =
                make_float2(acc[mt][nt][0] * alpha, acc[mt][nt][1] * alpha);
            *reinterpret_cast<float2*>(Cb + (size_t)(row + 8) * ldc + col) =
                make_float2(acc[mt][nt][2] * alpha, acc[mt][nt][3] * alpha);
        }
    }
}

__global__ __launch_bounds__(NTHREADS) void k_proj_q(const float* __restrict__ x,
                                                     const float* __restrict__ W) {
    gemm_fp16_nt(x, CDIM, W, CDIM, g_q, CDIM, CDIM, 1.0f);
}
__global__ __launch_bounds__(NTHREADS) void k_proj_kv(const float* __restrict__ x,
                                                      const float* __restrict__ Wk,
                                                      const float* __restrict__ Wv) {
    const float* W = blockIdx.z ? Wv : Wk;
    float* O = blockIdx.z ? g_v : g_k;
    gemm_fp16_nt(x, CDIM, W, CDIM, O, KVDIM, CDIM, 1.0f);
}
__global__ __launch_bounds__(NTHREADS) void k_oproj(const float* __restrict__ Wo,
                                                    float* __restrict__ out) {
    gemm_fp16_nt(g_att, CDIM, Wo, CDIM, out, CDIM, CDIM, 1.0f);
}

// ---------------------------------------------------------------------------
// Fused flash attention: per (b,h, m-block of 128 q rows), loop over 16 KV
// tiles of 128: S = Q.K^T (3-term fp16), online softmax, O += P.V (3-term).
// Warp layout: warp w owns q-rows w*16..w*16+15, full N.
// grid (SEQ/128, BATCH*NHEAD), 256 threads, 1 CTA/SM (209KB smem).
// ---------------------------------------------------------------------------
__global__ __launch_bounds__(256, 1) void k_flash() {
    extern __shared__ uint32_t fsm[];
    const uint32_t ub = s2u(fsm);
    uint32_t* sQh = fsm;
    uint32_t* sQl = fsm + FPL;
    uint32_t* sKh = fsm + 2 * FPL;
    uint32_t* sKl = fsm + 3 * FPL;
    uint32_t* sVh = fsm + 4 * FPL;
    uint32_t* sVl = fsm + 5 * FPL;

    const int tid  = threadIdx.x;
    const int lane = tid & 31;
    const int warp = tid >> 5;
    const int gid  = lane >> 2;
    const int tig  = lane & 3;
    const int z = blockIdx.y, b = z >> 4, h = z & 15, g = h >> 2;

    // loader: thread -> row r, 64-float half ch
    const int r  = tid >> 1;
    const int ch = tid & 1;
    const int wo = r * FW + ch * 32;

    // stage Q (scaled) once
    {
        const float* qp = g_q + ((size_t)(b * SEQ + blockIdx.x * 128 + r)) * CDIM
                        + h * HDIM + ch * 64;
#pragma unroll
        for (int i = 0; i < 16; i++) {
            float4 v = *reinterpret_cast<const float4*>(qp + 4 * i);
            v.x *= SCALE; v.y *= SCALE; v.z *= SCALE; v.w *= SCALE;
            uint32_t h0, l0, h1, l1;
            split2(v.x, v.y, h0, l0);
            split2(v.z, v.w, h1, l1);
            sQh[wo + 2 * i] = h0; sQh[wo + 2 * i + 1] = h1;
            sQl[wo + 2 * i] = l0; sQl[wo + 2 * i + 1] = l1;
        }
    }

    float accO[16][4];
#pragma unroll
    for (int nt = 0; nt < 16; nt++)
#pragma unroll
        for (int q = 0; q < 4; q++) accO[nt][q] = 0.0f;
    float m0 = -INFINITY, m1 = -INFINITY, l0s = 0.0f, l1s = 0.0f;

    const float* kbase = g_k + (size_t)b * SEQ * KVDIM + g * HDIM;
    const float* vtb   = g_vt + ((size_t)b * KVDIM + g * HDIM) * SEQ;

    __syncthreads();

#pragma unroll 1
    for (int kt = 0; kt < SEQ / 128; kt++) {
        // stage K tile [t][d] and Vt tile [d][t]
        {
            const float* kp = kbase + (size_t)(kt * 128 + r) * KVDIM + ch * 64;
            const float* vp = vtb + (size_t)r * SEQ + kt * 128 + ch * 64;
#pragma unroll
            for (int i = 0; i < 16; i++) {
                float4 v = *reinterpret_cast<const float4*>(kp + 4 * i);
                uint32_t h0, l0, h1, l1;
                split2(v.x, v.y, h0, l0);
                split2(v.z, v.w, h1, l1);
                sKh[wo + 2 * i] = h0; sKh[wo + 2 * i + 1] = h1;
                sKl[wo + 2 * i] = l0; sKl[wo + 2 * i + 1] = l1;
                float4 w = *reinterpret_cast<const float4*>(vp + 4 * i);
                split2(w.x, w.y, h0, l0);
                split2(w.z, w.w, h1, l1);
                sVh[wo + 2 * i] = h0; sVh[wo + 2 * i + 1] = h1;
                sVl[wo + 2 * i] = l0; sVl[wo + 2 * i + 1] = l1;
            }
        }
        __syncthreads();

        // S = Q.K^T  (per warp: 16 rows x 128 cols, 16 n8 tiles)
        float accS[16][4];
#pragma unroll
        for (int nt = 0; nt < 16; nt++)
#pragma unroll
            for (int q = 0; q < 4; q++) accS[nt][q] = 0.0f;

#pragma unroll
        for (int s = 0; s < 8; s++) {
            const uint32_t aoff =
                (uint32_t)((warp * 16 + (lane & 15)) * FW + s * 8 + (lane >> 4) * 4) * 4u;
            uint32_t qh0, qh1, qh2, qh3, ql0, ql1, ql2, ql3;
            ldsm4(ub + aoff,               qh0, qh1, qh2, qh3);
            ldsm4(ub + 4u * FPL + aoff,    ql0, ql1, ql2, ql3);   // sQl plane
#pragma unroll
            for (int nt = 0; nt < 16; nt++) {
                const int wi = (nt * 8 + gid) * FW + s * 8 + tig;
                uint32_t bh0 = sKh[wi], bh1 = sKh[wi + 4];
                uint32_t bl0 = sKl[wi], bl1 = sKl[wi + 4];
                mma16(accS[nt], qh0, qh1, qh2, qh3, bh0, bh1);
                mma16(accS[nt], qh0, qh1, qh2, qh3, bl0, bl1);
                mma16(accS[nt], ql0, ql1, ql2, ql3, bh0, bh1);
            }
        }

        // online softmax (rows g and g+8 of this warp's 16)
        float r0 = -INFINITY, r1 = -INFINITY;
#pragma unroll
        for (int nt = 0; nt < 16; nt++) {
            r0 = fmaxf(r0, fmaxf(accS[nt][0], accS[nt][1]));
            r1 = fmaxf(r1, fmaxf(accS[nt][2], accS[nt][3]));
        }
        r0 = fmaxf(r0, __shfl_xor_sync(0xFFFFFFFFu, r0, 1));
        r0 = fmaxf(r0, __shfl_xor_sync(0xFFFFFFFFu, r0, 2));
        r1 = fmaxf(r1, __shfl_xor_sync(0xFFFFFFFFu, r1, 1));
        r1 = fmaxf(r1, __shfl_xor_sync(0xFFFFFFFFu, r1, 2));
        const float mn0 = fmaxf(m0, r0), mn1 = fmaxf(m1, r1);
        const float a0 = expf(m0 - mn0), a1 = expf(m1 - mn1);
        m0 = mn0; m1 = mn1;

        float s0 = 0.0f, s1 = 0.0f;
#pragma unroll
        for (int nt = 0; nt < 16; nt++) {
            accS[nt][0] = expf(accS[nt][0] - mn0);
            accS[nt][1] = expf(accS[nt][1] - mn0);
            accS[nt][2] = expf(accS[nt][2] - mn1);
            accS[nt][3] = expf(accS[nt][3] - mn1);
            s0 += accS[nt][0] + accS[nt][1];
            s1 += accS[nt][2] + accS[nt][3];
        }
        s0 += __shfl_xor_sync(0xFFFFFFFFu, s0, 1);
        s0 += __shfl_xor_sync(0xFFFFFFFFu, s0, 2);
        s1 += __shfl_xor_sync(0xFFFFFFFFu, s1, 1);
        s1 += __shfl_xor_sync(0xFFFFFFFFu, s1, 2);
        l0s = l0s * a0 + s0;
        l1s = l1s * a1 + s1;

#pragma unroll
        for (int nt = 0; nt < 16; nt++) {
            accO[nt][0] *= a0; accO[nt][1] *= a0;
            accO[nt][2] *= a1; accO[nt][3] *= a1;
        }

        // O += P.V  (P a-frags built in-register from accS; V b-frags from sVh/sVl)
#pragma unroll
        for (int s = 0; s < 8; s++) {
            uint32_t pa0, pa1, pa2, pa3, pl0, pl1, pl2, pl3;
            split2(accS[2 * s][0],     accS[2 * s][1],     pa0, pl0);
            split2(accS[2 * s][2],     accS[2 * s][3],     pa1, pl1);
            split2(accS[2 * s + 1][0], accS[2 * s + 1][1], pa2, pl2);
            split2(accS[2 * s + 1][2], accS[2 * s + 1][3], pa3, pl3);
#pragma unroll
            for (int nt = 0; nt < 16; nt++) {
                const int wi = (nt * 8 + gid) * FW + s * 8 + tig;
                uint32_t vh0 = sVh[wi], vh1 = sVh[wi + 4];
                uint32_t vl0 = sVl[wi], vl1 = sVl[wi + 4];
                mma16(accO[nt], pa0, pa1, pa2, pa3, vh0, vh1);
                mma16(accO[nt], pa0, pa1, pa2, pa3, vl0, vl1);
                mma16(accO[nt], pl0, pl1, pl2, pl3, vh0, vh1);
            }
        }
        __syncthreads();
    }

    // epilogue: O /= l, write to g_att
    const float i0 = 1.0f / l0s, i1 = 1.0f / l1s;
    const int row0 = blockIdx.x * 128 + warp * 16 + gid;
    float* ob = g_att + ((size_t)(b * SEQ + row0)) * CDIM + h * HDIM;
#pragma unroll
    for (int nt = 0; nt < 16; nt++) {
        const int col = nt * 8 + 2 * tig;
        *reinterpret_cast<float2*>(ob + col) =
            make_float2(accO[nt][0] * i0, accO[nt][1] * i0);
        *reinterpret_cast<float2*>(ob + 8 * CDIM + col) =
            make_float2(accO[nt][2] * i1, accO[nt][3] * i1);
    }
}

// ---------------------------------------------------------------------------
// V transpose: g_vt[b][d][t] = g_v[b][t][d]
// ---------------------------------------------------------------------------
__global__ void k_vt() {
    __shared__ float tile[32][33];
    const int b  = blockIdx.z;
    const int t0 = blockIdx.x * 32;
    const int d0 = blockIdx.y * 32;
    const int tx = threadIdx.x, ty = threadIdx.y;
#pragma unroll
    for (int j = 0; j < 4; j++) {
        tile[ty + 8 * j][tx] =
            g_v[((size_t)b * SEQ + t0 + ty + 8 * j) * KVDIM + d0 + tx];
    }
    __syncthreads();
#pragma unroll
    for (int j = 0; j < 4; j++) {
        g_vt[((size_t)b * KVDIM + d0 + ty + 8 * j) * SEQ + t0 + tx] =
            tile[tx][ty + 8 * j];
    }
}

// ---------------------------------------------------------------------------
// RoPE (Llama half-rotation), in-place on q and k; fp64 tables.
// ---------------------------------------------------------------------------
__global__ void k_rope(const int* __restrict__ start_pos) {
    __shared__ float cs[HDIM / 2], sn[HDIM / 2];
    const int bt  = blockIdx.x;
    const int t   = bt & (SEQ - 1);
    const int tid = threadIdx.x;

    if (tid < HDIM / 2) {
        double inv = pow(10000.0, -(double)(2 * tid) / (double)HDIM);
        double ang = (double)(t + start_pos[0]) * inv;
        cs[tid] = (float)cos(ang);
        sn[tid] = (float)sin(ang);
    }
    __syncthreads();

    float* qrow = g_q + (size_t)bt * CDIM;
    for (int idx = tid; idx < NHEAD * (HDIM / 2); idx += blockDim.x) {
        int h = idx >> 6, i = idx & 63;
        float x1 = qrow[h * HDIM + i];
        float x2 = qrow[h * HDIM + i + 64];
        qrow[h * HDIM + i]      = x1 * cs[i] - x2 * sn[i];
        qrow[h * HDIM + i + 64] = x2 * cs[i] + x1 * sn[i];
    }
    float* krow = g_k + (size_t)bt * KVDIM;
    for (int idx = tid; idx < NKV * (HDIM / 2); idx += blockDim.x) {
        int h = idx >> 6, i = idx & 63;
        float x1 = krow[h * HDIM + i];
        float x2 = krow[h * HDIM + i + 64];
        krow[h * HDIM + i]      = x1 * cs[i] - x2 * sn[i];
        krow[h * HDIM + i + 64] = x2 * cs[i] + x1 * sn[i];
    }
}

// ---------------------------------------------------------------------------
// Entry point
// ---------------------------------------------------------------------------
extern "C" void kernel_launch(void* const* d_in, const int* in_sizes, int n_in,
                              void* d_out, int out_size) {
    const float* x  = (const float*)d_in[0];
    const float* Wq = (const float*)d_in[1];
    const float* Wk = (const float*)d_in[2];
    const float* Wv = (const float*)d_in[3];
    const float* Wo = (const float*)d_in[4];
    const int*   sp = (const int*)d_in[5];
    float* out = (float*)d_out;

    static int smem_set = 0;
    if (!smem_set) {
        cudaFuncSetAttribute(k_flash, cudaFuncAttributeMaxDynamicSharedMemorySize,
                             SMEM_FLASH);
        smem_set = 1;
    }

    k_proj_q<<<dim3(CDIM / BN, MROWS / BM), NTHREADS>>>(x, Wq);
    k_proj_kv<<<dim3(KVDIM / BN, MROWS / BM, 2), NTHREADS>>>(x, Wk, Wv);

    k_rope<<<MROWS, 256>>>(sp);
    k_vt<<<dim3(SEQ / 32, KVDIM / 32, BATCH), dim3(32, 8)>>>();

    k_flash<<<dim3(SEQ / 128, BATCH * NHEAD), 256, SMEM_FLASH>>>();

    k_oproj<<<dim3(CDIM / BN, MROWS / BM), NTHREADS>>>(Wo, out);
}

// round 10
// speedup vs baseline: 2.2416x; 1.1465x over previous
#include <cuda_runtime.h>
#include <cuda_fp16.h>
#include <math.h>
#include <stdint.h>

// Problem constants
#define BATCH   2
#define SEQ     2048
#define CDIM    2048
#define NHEAD   16
#define NKV     4
#define HDIM    128
#define MROWS   (BATCH * SEQ)          // 4096
#define KVDIM   (NKV * HDIM)           // 512
#define SCALE   0.08838834764831845f   // 1/sqrt(128)

// Projection GEMM tiling
#define BM 128
#define BN 128
#define BK 32
#define RS 20
#define PLANE_W (128 * RS)
#define PLANE_B (PLANE_W * 4)
#define NTHREADS 256

// Flash kernel smem: 6 planes of [128 rows x 68 words] (64 data words = 128 halfs)
#define FW  68
#define FPL (128 * FW)                 // words per plane
#define SMEM_FLASH (6 * FPL * 4)       // 208896 bytes

// ---------------------------------------------------------------------------
// Static device scratch
// ---------------------------------------------------------------------------
__device__ float  g_q[(size_t)MROWS * CDIM];             // 32 MB (pre-rope fp32)
__device__ float  g_k[(size_t)MROWS * KVDIM];            // 8 MB
__device__ float  g_v[(size_t)MROWS * KVDIM];            // 8 MB
__device__ float  g_att[(size_t)MROWS * CDIM];           // 32 MB
__device__ __half g_qh[(size_t)MROWS * CDIM];            // 16 MB (scaled, rope'd)
__device__ __half g_ql[(size_t)MROWS * CDIM];            // 16 MB
__device__ __half g_kh[(size_t)MROWS * KVDIM];           // 4 MB (rope'd)
__device__ __half g_kl[(size_t)MROWS * KVDIM];           // 4 MB
__device__ __half g_vth[(size_t)BATCH * KVDIM * SEQ];    // 4 MB (V^T)
__device__ __half g_vtl[(size_t)BATCH * KVDIM * SEQ];    // 4 MB

// ---------------------------------------------------------------------------
// Helpers
// ---------------------------------------------------------------------------
__device__ __forceinline__ uint32_t s2u(const void* p) {
    uint32_t a;
    asm("{ .reg .u64 t; cvta.to.shared.u64 t, %1; cvt.u32.u64 %0, t; }" : "=r"(a) : "l"(p));
    return a;
}
__device__ __forceinline__ void split2(float x, float y, uint32_t& hw, uint32_t& lw) {
    __half2 h = __floats2half2_rn(x, y);
    float2 hf = __half22float2(h);
    __half2 l = __floats2half2_rn(x - hf.x, y - hf.y);
    hw = *reinterpret_cast<uint32_t*>(&h);
    lw = *reinterpret_cast<uint32_t*>(&l);
}
__device__ __forceinline__ void ldsm4(uint32_t addr, uint32_t& r0, uint32_t& r1,
                                      uint32_t& r2, uint32_t& r3) {
    asm volatile("ldmatrix.sync.aligned.m8n8.x4.shared.b16 {%0,%1,%2,%3}, [%4];"
                 : "=r"(r0), "=r"(r1), "=r"(r2), "=r"(r3) : "r"(addr));
}
__device__ __forceinline__ void mma16(float* d, uint32_t a0, uint32_t a1, uint32_t a2,
                                      uint32_t a3, uint32_t b0, uint32_t b1) {
    asm volatile(
        "mma.sync.aligned.m16n8k16.row.col.f32.f16.f16.f32 "
        "{%0,%1,%2,%3}, {%4,%5,%6,%7}, {%8,%9}, {%0,%1,%2,%3};"
        : "+f"(d[0]), "+f"(d[1]), "+f"(d[2]), "+f"(d[3])
        : "r"(a0), "r"(a1), "r"(a2), "r"(a3), "r"(b0), "r"(b1));
}
__device__ __forceinline__ void cp16(uint32_t dst, const void* src) {
    asm volatile("cp.async.cg.shared.global [%0], [%1], 16;" :: "r"(dst), "l"(src));
}
#define CP_COMMIT() asm volatile("cp.async.commit_group;" ::: "memory")
#define CP_WAIT0()  asm volatile("cp.async.wait_group 0;" ::: "memory")

// ---------------------------------------------------------------------------
// NT GEMM core (projections): C = A * B^T, 3-term fp16 split.
// Block coords passed explicitly so callers can remap blockIdx.
// ---------------------------------------------------------------------------
__device__ void gemm_fp16_nt(const float* __restrict__ A, int lda,
                             const float* __restrict__ B, int ldb,
                             float* __restrict__ C, int ldc,
                             int K, int bxn, int bym)
{
    __shared__ uint32_t sm[4][PLANE_W];
    uint32_t* sAh = sm[0];
    uint32_t* sAl = sm[1];
    uint32_t* sBh = sm[2];
    uint32_t* sBl = sm[3];
    const uint32_t ub = s2u(sm);

    const int tid  = threadIdx.x;
    const int lane = tid & 31;
    const int warp = tid >> 5;
    const int gid  = lane >> 2;
    const int tig  = lane & 3;
    const int wm   = (warp & 1) * 64;
    const int wn   = (warp >> 1) * 32;

    const int r  = tid >> 1;
    const int ch = tid & 1;
    const float* Ap = A + (size_t)(bym * BM + r) * lda + ch * 16;
    const float* Bp = B + (size_t)(bxn * BN + r) * ldb + ch * 16;

    float acc[4][4][4];
#pragma unroll
    for (int i = 0; i < 4; i++)
#pragma unroll
        for (int j = 0; j < 4; j++)
#pragma unroll
            for (int q = 0; q < 4; q++) acc[i][j][q] = 0.0f;

    float4 pa[4], pb[4];
#pragma unroll
    for (int i = 0; i < 4; i++) {
        pa[i] = *reinterpret_cast<const float4*>(Ap + 4 * i);
        pb[i] = *reinterpret_cast<const float4*>(Bp + 4 * i);
    }

    const int wo = r * RS + ch * 8;

    for (int kc = 0; kc < K; kc += BK) {
        {
            uint32_t hw[8], lw[8];
#pragma unroll
            for (int i = 0; i < 4; i++) {
                split2(pa[i].x, pa[i].y, hw[2 * i],     lw[2 * i]);
                split2(pa[i].z, pa[i].w, hw[2 * i + 1], lw[2 * i + 1]);
            }
            *reinterpret_cast<uint4*>(&sAh[wo])     = make_uint4(hw[0], hw[1], hw[2], hw[3]);
            *reinterpret_cast<uint4*>(&sAh[wo + 4]) = make_uint4(hw[4], hw[5], hw[6], hw[7]);
            *reinterpret_cast<uint4*>(&sAl[wo])     = make_uint4(lw[0], lw[1], lw[2], lw[3]);
            *reinterpret_cast<uint4*>(&sAl[wo + 4]) = make_uint4(lw[4], lw[5], lw[6], lw[7]);
#pragma unroll
            for (int i = 0; i < 4; i++) {
                split2(pb[i].x, pb[i].y, hw[2 * i],     lw[2 * i]);
                split2(pb[i].z, pb[i].w, hw[2 * i + 1], lw[2 * i + 1]);
            }
            *reinterpret_cast<uint4*>(&sBh[wo])     = make_uint4(hw[0], hw[1], hw[2], hw[3]);
            *reinterpret_cast<uint4*>(&sBh[wo + 4]) = make_uint4(hw[4], hw[5], hw[6], hw[7]);
            *reinterpret_cast<uint4*>(&sBl[wo])     = make_uint4(lw[0], lw[1], lw[2], lw[3]);
            *reinterpret_cast<uint4*>(&sBl[wo + 4]) = make_uint4(lw[4], lw[5], lw[6], lw[7]);
        }
        __syncthreads();

        if (kc + BK < K) {
#pragma unroll
            for (int i = 0; i < 4; i++) {
                pa[i] = *reinterpret_cast<const float4*>(Ap + kc + BK + 4 * i);
                pb[i] = *reinterpret_cast<const float4*>(Bp + kc + BK + 4 * i);
            }
        }

#pragma unroll
        for (int ks = 0; ks < 2; ks++) {
            const int kw = ks * 8;
            uint32_t bh[4][2], bl[4][2];
#pragma unroll
            for (int nt = 0; nt < 4; nt++) {
                const int bidx = (wn + nt * 8 + gid) * RS + kw + tig;
                bh[nt][0] = sBh[bidx];
                bh[nt][1] = sBh[bidx + 4];
                bl[nt][0] = sBl[bidx];
                bl[nt][1] = sBl[bidx + 4];
            }
#pragma unroll
            for (int mt = 0; mt < 4; mt++) {
                const int arow = wm + mt * 16 + (lane & 15);
                const uint32_t aoff = (uint32_t)(arow * RS + kw + (lane >> 4) * 4) * 4u;
                uint32_t ah0, ah1, ah2, ah3, al0, al1, al2, al3;
                ldsm4(ub + aoff,            ah0, ah1, ah2, ah3);
                ldsm4(ub + PLANE_B + aoff,  al0, al1, al2, al3);
#pragma unroll
                for (int nt = 0; nt < 4; nt++) {
                    mma16(acc[mt][nt], ah0, ah1, ah2, ah3, bh[nt][0], bh[nt][1]);
                    mma16(acc[mt][nt], ah0, ah1, ah2, ah3, bl[nt][0], bl[nt][1]);
                    mma16(acc[mt][nt], al0, al1, al2, al3, bh[nt][0], bh[nt][1]);
                }
            }
        }
        __syncthreads();
    }

    float* Cb = C + (size_t)bym * BM * ldc + (size_t)bxn * BN;
#pragma unroll
    for (int mt = 0; mt < 4; mt++) {
        const int row = wm + mt * 16 + gid;
#pragma unroll
        for (int nt = 0; nt < 4; nt++) {
            const int col = wn + nt * 8 + 2 * tig;
            *reinterpret_cast<float2*>(Cb + (size_t)row * ldc + col) =
                make_float2(acc[mt][nt][0], acc[mt][nt][1]);
            *reinterpret_cast<float2*>(Cb + (size_t)(row + 8) * ldc + col) =
                make_float2(acc[mt][nt][2], acc[mt][nt][3]);
        }
    }
}

// Fused Q/K/V projections: grid.x = 24 (16 Q n-blocks, 4 K, 4 V).
__global__ __launch_bounds__(NTHREADS) void k_qkv(const float* __restrict__ x,
                                                  const float* __restrict__ Wq,
                                                  const float* __restrict__ Wk,
                                                  const float* __restrict__ Wv) {
    const int bx = blockIdx.x;
    const float* W;
    float* O;
    int ldo, nb;
    if (bx < 16)      { W = Wq; O = g_q; ldo = CDIM;  nb = bx; }
    else if (bx < 20) { W = Wk; O = g_k; ldo = KVDIM; nb = bx - 16; }
    else              { W = Wv; O = g_v; ldo = KVDIM; nb = bx - 20; }
    gemm_fp16_nt(x, CDIM, W, CDIM, O, ldo, CDIM, nb, blockIdx.y);
}
__global__ __launch_bounds__(NTHREADS) void k_oproj(const float* __restrict__ Wo,
                                                    float* __restrict__ out) {
    gemm_fp16_nt(g_att, CDIM, Wo, CDIM, out, CDIM, CDIM, blockIdx.x, blockIdx.y);
}

// ---------------------------------------------------------------------------
// RoPE + fp16 pre-split: reads fp32 q/k, writes scaled split q and split k
// as fp16 hi/lo planes (flash consumes these directly).
// ---------------------------------------------------------------------------
__global__ void k_rope_split(const int* __restrict__ start_pos) {
    __shared__ float cs[HDIM / 2], sn[HDIM / 2];
    const int bt  = blockIdx.x;
    const int t   = bt & (SEQ - 1);
    const int tid = threadIdx.x;

    if (tid < HDIM / 2) {
        double inv = pow(10000.0, -(double)(2 * tid) / (double)HDIM);
        double ang = (double)(t + start_pos[0]) * inv;
        cs[tid] = (float)cos(ang);
        sn[tid] = (float)sin(ang);
    }
    __syncthreads();

    const float* qrow = g_q + (size_t)bt * CDIM;
    __half* qh = g_qh + (size_t)bt * CDIM;
    __half* ql = g_ql + (size_t)bt * CDIM;
    for (int idx = tid; idx < NHEAD * (HDIM / 2); idx += blockDim.x) {
        int h = idx >> 6, i = idx & 63;
        float x1 = qrow[h * HDIM + i];
        float x2 = qrow[h * HDIM + i + 64];
        float r1 = (x1 * cs[i] - x2 * sn[i]) * SCALE;
        float r2 = (x2 * cs[i] + x1 * sn[i]) * SCALE;
        __half h1 = __float2half_rn(r1);
        __half h2 = __float2half_rn(r2);
        qh[h * HDIM + i]      = h1;
        ql[h * HDIM + i]      = __float2half_rn(r1 - __half2float(h1));
        qh[h * HDIM + i + 64] = h2;
        ql[h * HDIM + i + 64] = __float2half_rn(r2 - __half2float(h2));
    }

    const float* krow = g_k + (size_t)bt * KVDIM;
    __half* kh = g_kh + (size_t)bt * KVDIM;
    __half* kl = g_kl + (size_t)bt * KVDIM;
    for (int idx = tid; idx < NKV * (HDIM / 2); idx += blockDim.x) {
        int h = idx >> 6, i = idx & 63;
        float x1 = krow[h * HDIM + i];
        float x2 = krow[h * HDIM + i + 64];
        float r1 = x1 * cs[i] - x2 * sn[i];
        float r2 = x2 * cs[i] + x1 * sn[i];
        __half h1 = __float2half_rn(r1);
        __half h2 = __float2half_rn(r2);
        kh[h * HDIM + i]      = h1;
        kl[h * HDIM + i]      = __float2half_rn(r1 - __half2float(h1));
        kh[h * HDIM + i + 64] = h2;
        kl[h * HDIM + i + 64] = __float2half_rn(r2 - __half2float(h2));
    }
}

// ---------------------------------------------------------------------------
// V transpose + split: g_vth/l[b][d][t] = split(g_v[b][t][d])
// ---------------------------------------------------------------------------
__global__ void k_vt2() {
    __shared__ float tile[32][33];
    const int b  = blockIdx.z;
    const int t0 = blockIdx.x * 32;
    const int d0 = blockIdx.y * 32;
    const int tx = threadIdx.x, ty = threadIdx.y;
#pragma unroll
    for (int j = 0; j < 4; j++) {
        tile[ty + 8 * j][tx] =
            g_v[((size_t)b * SEQ + t0 + ty + 8 * j) * KVDIM + d0 + tx];
    }
    __syncthreads();
#pragma unroll
    for (int j = 0; j < 4; j++) {
        float v = tile[tx][ty + 8 * j];
        __half hh = __float2half_rn(v);
        size_t o = ((size_t)b * KVDIM + d0 + ty + 8 * j) * SEQ + t0 + tx;
        g_vth[o] = hh;
        g_vtl[o] = __float2half_rn(v - __half2float(hh));
    }
}

// ---------------------------------------------------------------------------
// Fused flash attention. Staging is pure cp.async of pre-split fp16 planes.
// grid (SEQ/128, BATCH*NHEAD), 256 threads, 1 CTA/SM (209KB smem).
// ---------------------------------------------------------------------------
__global__ __launch_bounds__(256, 1) void k_flash() {
    extern __shared__ uint32_t fsm[];
    const uint32_t ub = s2u(fsm);
    uint32_t* sKh = fsm + 2 * FPL;
    uint32_t* sKl = fsm + 3 * FPL;
    uint32_t* sVh = fsm + 4 * FPL;
    uint32_t* sVl = fsm + 5 * FPL;

    const int tid  = threadIdx.x;
    const int lane = tid & 31;
    const int warp = tid >> 5;
    const int gid  = lane >> 2;
    const int tig  = lane & 3;
    const int z = blockIdx.y, b = z >> 4, h = z & 15, g = h >> 2;

    const int r  = tid >> 1;
    const int ch = tid & 1;
    const uint32_t dwo = (uint32_t)(r * FW + ch * 32) * 4u;  // byte offset in a plane

    // stage Q (pre-scaled, pre-split) once: planes 0 (hi) and 1 (lo)
    {
        const __half* qh = g_qh + ((size_t)(b * SEQ + blockIdx.x * 128 + r)) * CDIM
                         + h * HDIM + ch * 64;
        const __half* ql = g_ql + ((size_t)(b * SEQ + blockIdx.x * 128 + r)) * CDIM
                         + h * HDIM + ch * 64;
#pragma unroll
        for (int j = 0; j < 8; j++) {
            cp16(ub + dwo + 16u * j,                 qh + 8 * j);
            cp16(ub + (uint32_t)FPL * 4u + dwo + 16u * j, ql + 8 * j);
        }
        CP_COMMIT();
    }

    float accO[16][4];
#pragma unroll
    for (int nt = 0; nt < 16; nt++)
#pragma unroll
        for (int q = 0; q < 4; q++) accO[nt][q] = 0.0f;
    float m0 = -INFINITY, m1 = -INFINITY, l0s = 0.0f, l1s = 0.0f;

    const __half* khb = g_kh + (size_t)b * SEQ * KVDIM + g * HDIM;
    const __half* klb = g_kl + (size_t)b * SEQ * KVDIM + g * HDIM;
    const __half* vhb = g_vth + ((size_t)b * KVDIM + g * HDIM) * SEQ;
    const __half* vlb = g_vtl + ((size_t)b * KVDIM + g * HDIM) * SEQ;

    CP_WAIT0();
    __syncthreads();

#pragma unroll 1
    for (int kt = 0; kt < SEQ / 128; kt++) {
        // stage K tile [t][d] and Vt tile [d][t] via cp.async (planes 2..5)
        {
            const __half* kh = khb + (size_t)(kt * 128 + r) * KVDIM + ch * 64;
            const __half* kl = klb + (size_t)(kt * 128 + r) * KVDIM + ch * 64;
            const __half* vh = vhb + (size_t)r * SEQ + kt * 128 + ch * 64;
            const __half* vl = vlb + (size_t)r * SEQ + kt * 128 + ch * 64;
#pragma unroll
            for (int j = 0; j < 8; j++) {
                cp16(ub + 2u * FPL * 4u + dwo + 16u * j, kh + 8 * j);
                cp16(ub + 3u * FPL * 4u + dwo + 16u * j, kl + 8 * j);
                cp16(ub + 4u * FPL * 4u + dwo + 16u * j, vh + 8 * j);
                cp16(ub + 5u * FPL * 4u + dwo + 16u * j, vl + 8 * j);
            }
            CP_COMMIT();
            CP_WAIT0();
        }
        __syncthreads();

        // S = Q.K^T  (per warp: 16 rows x 128 cols, 16 n8 tiles)
        float accS[16][4];
#pragma unroll
        for (int nt = 0; nt < 16; nt++)
#pragma unroll
            for (int q = 0; q < 4; q++) accS[nt][q] = 0.0f;

#pragma unroll
        for (int s = 0; s < 8; s++) {
            const uint32_t aoff =
                (uint32_t)((warp * 16 + (lane & 15)) * FW + s * 8 + (lane >> 4) * 4) * 4u;
            uint32_t qh0, qh1, qh2, qh3, ql0, ql1, ql2, ql3;
            ldsm4(ub + aoff,                    qh0, qh1, qh2, qh3);
            ldsm4(ub + (uint32_t)FPL * 4u + aoff, ql0, ql1, ql2, ql3);
#pragma unroll
            for (int nt = 0; nt < 16; nt++) {
                const int wi = (nt * 8 + gid) * FW + s * 8 + tig;
                uint32_t bh0 = sKh[wi], bh1 = sKh[wi + 4];
                uint32_t bl0 = sKl[wi], bl1 = sKl[wi + 4];
                mma16(accS[nt], qh0, qh1, qh2, qh3, bh0, bh1);
                mma16(accS[nt], qh0, qh1, qh2, qh3, bl0, bl1);
                mma16(accS[nt], ql0, ql1, ql2, ql3, bh0, bh1);
            }
        }

        // online softmax (rows g and g+8 of this warp's 16)
        float r0 = -INFINITY, r1 = -INFINITY;
#pragma unroll
        for (int nt = 0; nt < 16; nt++) {
            r0 = fmaxf(r0, fmaxf(accS[nt][0], accS[nt][1]));
            r1 = fmaxf(r1, fmaxf(accS[nt][2], accS[nt][3]));
        }
        r0 = fmaxf(r0, __shfl_xor_sync(0xFFFFFFFFu, r0, 1));
        r0 = fmaxf(r0, __shfl_xor_sync(0xFFFFFFFFu, r0, 2));
        r1 = fmaxf(r1, __shfl_xor_sync(0xFFFFFFFFu, r1, 1));
        r1 = fmaxf(r1, __shfl_xor_sync(0xFFFFFFFFu, r1, 2));
        const float mn0 = fmaxf(m0, r0), mn1 = fmaxf(m1, r1);
        const float a0 = expf(m0 - mn0), a1 = expf(m1 - mn1);
        m0 = mn0; m1 = mn1;

        float s0 = 0.0f, s1 = 0.0f;
#pragma unroll
        for (int nt = 0; nt < 16; nt++) {
            accS[nt][0] = expf(accS[nt][0] - mn0);
            accS[nt][1] = expf(accS[nt][1] - mn0);
            accS[nt][2] = expf(accS[nt][2] - mn1);
            accS[nt][3] = expf(accS[nt][3] - mn1);
            s0 += accS[nt][0] + accS[nt][1];
            s1 += accS[nt][2] + accS[nt][3];
        }
        s0 += __shfl_xor_sync(0xFFFFFFFFu, s0, 1);
        s0 += __shfl_xor_sync(0xFFFFFFFFu, s0, 2);
        s1 += __shfl_xor_sync(0xFFFFFFFFu, s1, 1);
        s1 += __shfl_xor_sync(0xFFFFFFFFu, s1, 2);
        l0s = l0s * a0 + s0;
        l1s = l1s * a1 + s1;

#pragma unroll
        for (int nt = 0; nt < 16; nt++) {
            accO[nt][0] *= a0; accO[nt][1] *= a0;
            accO[nt][2] *= a1; accO[nt][3] *= a1;
        }

        // O += P.V  (P a-frags built in-register from accS)
#pragma unroll
        for (int s = 0; s < 8; s++) {
            uint32_t pa0, pa1, pa2, pa3, pl0, pl1, pl2, pl3;
            split2(accS[2 * s][0],     accS[2 * s][1],     pa0, pl0);
            split2(accS[2 * s][2],     accS[2 * s][3],     pa1, pl1);
            split2(accS[2 * s + 1][0], accS[2 * s + 1][1], pa2, pl2);
            split2(accS[2 * s + 1][2], accS[2 * s + 1][3], pa3, pl3);
#pragma unroll
            for (int nt = 0; nt < 16; nt++) {
                const int wi = (nt * 8 + gid) * FW + s * 8 + tig;
                uint32_t vh0 = sVh[wi], vh1 = sVh[wi + 4];
                uint32_t vl0 = sVl[wi], vl1 = sVl[wi + 4];
                mma16(accO[nt], pa0, pa1, pa2, pa3, vh0, vh1);
                mma16(accO[nt], pa0, pa1, pa2, pa3, vl0, vl1);
                mma16(accO[nt], pl0, pl1, pl2, pl3, vh0, vh1);
            }
        }
        __syncthreads();
    }

    // epilogue: O /= l, write to g_att
    const float i0 = 1.0f / l0s, i1 = 1.0f / l1s;
    const int row0 = blockIdx.x * 128 + warp * 16 + gid;
    float* ob = g_att + ((size_t)(b * SEQ + row0)) * CDIM + h * HDIM;
#pragma unroll
    for (int nt = 0; nt < 16; nt++) {
        const int col = nt * 8 + 2 * tig;
        *reinterpret_cast<float2*>(ob + col) =
            make_float2(accO[nt][0] * i0, accO[nt][1] * i0);
        *reinterpret_cast<float2*>(ob + 8 * CDIM + col) =
            make_float2(accO[nt][2] * i1, accO[nt][3] * i1);
    }
}

// ---------------------------------------------------------------------------
// Entry point
// ---------------------------------------------------------------------------
extern "C" void kernel_launch(void* const* d_in, const int* in_sizes, int n_in,
                              void* d_out, int out_size) {
    const float* x  = (const float*)d_in[0];
    const float* Wq = (const float*)d_in[1];
    const float* Wk = (const float*)d_in[2];
    const float* Wv = (const float*)d_in[3];
    const float* Wo = (const float*)d_in[4];
    const int*   sp = (const int*)d_in[5];
    float* out = (float*)d_out;

    static int smem_set = 0;
    if (!smem_set) {
        cudaFuncSetAttribute(k_flash, cudaFuncAttributeMaxDynamicSharedMemorySize,
                             SMEM_FLASH);
        smem_set = 1;
    }

    k_qkv<<<dim3(24, MROWS / BM), NTHREADS>>>(x, Wq, Wk, Wv);
    k_rope_split<<<MROWS, 256>>>(sp);
    k_vt2<<<dim3(SEQ / 32, KVDIM / 32, BATCH), dim3(32, 8)>>>();
    k_flash<<<dim3(SEQ / 128, BATCH * NHEAD), 256, SMEM_FLASH>>>();
    k_oproj<<<dim3(CDIM / BN, MROWS / BM), NTHREADS>>>(Wo, out);
}

// round 11
// speedup vs baseline: 2.3672x; 1.0560x over previous
#include <cuda_runtime.h>
#include <cuda_fp16.h>
#include <math.h>
#include <stdint.h>

// Problem constants
#define BATCH   2
#define SEQ     2048
#define CDIM    2048
#define NHEAD   16
#define NKV     4
#define HDIM    128
#define MROWS   (BATCH * SEQ)          // 4096
#define KVDIM   (NKV * HDIM)           // 512
#define SCALE   0.08838834764831845f   // 1/sqrt(128)

// Projection GEMM tiling
#define BM 128
#define BN 128
#define BK 32
#define RS 20                          // words per smem row (16 data + 4 pad)
#define PLANE_W (128 * RS)
#define PLANE_B (PLANE_W * 4)          // 10240 B
#define SMEM_PROJ (2 * 4 * PLANE_B)    // 81920 B (double-buffered 4 planes)
#define NTHREADS 256

// Flash kernel smem: 6 planes of [128 rows x 68 words]
#define FW  68
#define FPL (128 * FW)
#define SMEM_FLASH (6 * FPL * 4)       // 208896 B

// ---------------------------------------------------------------------------
// Static device scratch
// ---------------------------------------------------------------------------
__device__ float  g_q[(size_t)MROWS * CDIM];             // fp32 q (pre-rope)
__device__ float  g_k[(size_t)MROWS * KVDIM];
__device__ float  g_v[(size_t)MROWS * KVDIM];
// pre-split fp16 hi/lo planes
__device__ __half g_xh[(size_t)MROWS * CDIM],  g_xl[(size_t)MROWS * CDIM];
__device__ __half g_wqh[(size_t)CDIM * CDIM],  g_wql[(size_t)CDIM * CDIM];
__device__ __half g_wkh[(size_t)KVDIM * CDIM], g_wkl[(size_t)KVDIM * CDIM];
__device__ __half g_wvh[(size_t)KVDIM * CDIM], g_wvl[(size_t)KVDIM * CDIM];
__device__ __half g_woh[(size_t)CDIM * CDIM],  g_wol[(size_t)CDIM * CDIM];
__device__ __half g_qh[(size_t)MROWS * CDIM],  g_ql[(size_t)MROWS * CDIM];
__device__ __half g_kh[(size_t)MROWS * KVDIM], g_kl[(size_t)MROWS * KVDIM];
__device__ __half g_vth[(size_t)BATCH * KVDIM * SEQ], g_vtl[(size_t)BATCH * KVDIM * SEQ];
__device__ __half g_ah[(size_t)MROWS * CDIM],  g_al[(size_t)MROWS * CDIM]; // attn out split

// ---------------------------------------------------------------------------
// Helpers
// ---------------------------------------------------------------------------
__device__ __forceinline__ uint32_t s2u(const void* p) {
    uint32_t a;
    asm("{ .reg .u64 t; cvta.to.shared.u64 t, %1; cvt.u32.u64 %0, t; }" : "=r"(a) : "l"(p));
    return a;
}
__device__ __forceinline__ void split2(float x, float y, uint32_t& hw, uint32_t& lw) {
    __half2 h = __floats2half2_rn(x, y);
    float2 hf = __half22float2(h);
    __half2 l = __floats2half2_rn(x - hf.x, y - hf.y);
    hw = *reinterpret_cast<uint32_t*>(&h);
    lw = *reinterpret_cast<uint32_t*>(&l);
}
__device__ __forceinline__ void ldsm4(uint32_t addr, uint32_t& r0, uint32_t& r1,
                                      uint32_t& r2, uint32_t& r3) {
    asm volatile("ldmatrix.sync.aligned.m8n8.x4.shared.b16 {%0,%1,%2,%3}, [%4];"
                 : "=r"(r0), "=r"(r1), "=r"(r2), "=r"(r3) : "r"(addr));
}
__device__ __forceinline__ void mma16(float* d, uint32_t a0, uint32_t a1, uint32_t a2,
                                      uint32_t a3, uint32_t b0, uint32_t b1) {
    asm volatile(
        "mma.sync.aligned.m16n8k16.row.col.f32.f16.f16.f32 "
        "{%0,%1,%2,%3}, {%4,%5,%6,%7}, {%8,%9}, {%0,%1,%2,%3};"
        : "+f"(d[0]), "+f"(d[1]), "+f"(d[2]), "+f"(d[3])
        : "r"(a0), "r"(a1), "r"(a2), "r"(a3), "r"(b0), "r"(b1));
}
__device__ __forceinline__ void cp16(uint32_t dst, const void* src) {
    asm volatile("cp.async.cg.shared.global [%0], [%1], 16;" :: "r"(dst), "l"(src));
}
#define CP_COMMIT() asm volatile("cp.async.commit_group;" ::: "memory")
#define CP_WAIT0()  asm volatile("cp.async.wait_group 0;" ::: "memory")
#define CP_WAIT1()  asm volatile("cp.async.wait_group 1;" ::: "memory")

// ---------------------------------------------------------------------------
// Elementwise fp16 hi/lo split: n4 float4's
// ---------------------------------------------------------------------------
__global__ __launch_bounds__(256) void k_split(const float4* __restrict__ src,
                                               uint2* __restrict__ h,
                                               uint2* __restrict__ l, int n4) {
    int i = blockIdx.x * 256 + threadIdx.x;
    if (i >= n4) return;
    float4 v = src[i];
    uint32_t h0, l0, h1, l1;
    split2(v.x, v.y, h0, l0);
    split2(v.z, v.w, h1, l1);
    h[i] = make_uint2(h0, h1);
    l[i] = make_uint2(l0, l1);
}

// ---------------------------------------------------------------------------
// NT GEMM core on pre-split fp16 planes, cp.async double-buffered staging.
// C[BM,BN] = A * B^T (3-term). lda/ldb in halfs.
// ---------------------------------------------------------------------------
__device__ void gemm_async_nt(const __half* __restrict__ Ah, const __half* __restrict__ Al,
                              int lda,
                              const __half* __restrict__ Bh, const __half* __restrict__ Bl,
                              int ldb,
                              float* __restrict__ C, int ldc,
                              int K, int bxn, int bym)
{
    extern __shared__ uint32_t psm[];
    const uint32_t ub = s2u(psm);

    const int tid  = threadIdx.x;
    const int lane = tid & 31;
    const int warp = tid >> 5;
    const int gid  = lane >> 2;
    const int tig  = lane & 3;
    const int wm   = (warp & 1) * 64;
    const int wn   = (warp >> 1) * 32;

    // stage mapping: thread -> row r, 16-half half-row hf
    const int r  = tid >> 1;
    const int hf = tid & 1;
    const __half* pAh = Ah + (size_t)(bym * BM + r) * lda + hf * 16;
    const __half* pAl = Al + (size_t)(bym * BM + r) * lda + hf * 16;
    const __half* pBh = Bh + (size_t)(bxn * BN + r) * ldb + hf * 16;
    const __half* pBl = Bl + (size_t)(bxn * BN + r) * ldb + hf * 16;
    const uint32_t dst0 = ub + (uint32_t)(r * RS + hf * 8) * 4u;

    float acc[4][4][4];
#pragma unroll
    for (int i = 0; i < 4; i++)
#pragma unroll
        for (int j = 0; j < 4; j++)
#pragma unroll
            for (int q = 0; q < 4; q++) acc[i][j][q] = 0.0f;

    const int NCC = K / BK;

    // prologue: stage chunk 0 into buffer 0
    {
        cp16(dst0,                 pAh);
        cp16(dst0 + 16,            pAh + 8);
        cp16(dst0 + PLANE_B,       pAl);
        cp16(dst0 + PLANE_B + 16,  pAl + 8);
        cp16(dst0 + 2 * PLANE_B,      pBh);
        cp16(dst0 + 2 * PLANE_B + 16, pBh + 8);
        cp16(dst0 + 3 * PLANE_B,      pBl);
        cp16(dst0 + 3 * PLANE_B + 16, pBl + 8);
        CP_COMMIT();
    }

    for (int kc = 0; kc < NCC; kc++) {
        if (kc + 1 < NCC) {  // stage next chunk into other buffer
            const uint32_t d = dst0 + (uint32_t)(((kc + 1) & 1) * 4 * PLANE_B);
            const int ko = (kc + 1) * BK;
            cp16(d,                 pAh + ko);
            cp16(d + 16,            pAh + ko + 8);
            cp16(d + PLANE_B,       pAl + ko);
            cp16(d + PLANE_B + 16,  pAl + ko + 8);
            cp16(d + 2 * PLANE_B,      pBh + ko);
            cp16(d + 2 * PLANE_B + 16, pBh + ko + 8);
            cp16(d + 3 * PLANE_B,      pBl + ko);
            cp16(d + 3 * PLANE_B + 16, pBl + ko + 8);
            CP_COMMIT();
            CP_WAIT1();
        } else {
            CP_WAIT0();
        }
        __syncthreads();

        const int bufw = (kc & 1) * 4 * PLANE_W;
        const uint32_t bufb = (uint32_t)(kc & 1) * 4u * PLANE_B;
        const uint32_t* sBh = psm + bufw + 2 * PLANE_W;
        const uint32_t* sBl = psm + bufw + 3 * PLANE_W;

#pragma unroll
        for (int ks = 0; ks < 2; ks++) {
            const int kw = ks * 8;
            uint32_t bh[4][2], bl[4][2];
#pragma unroll
            for (int nt = 0; nt < 4; nt++) {
                const int bidx = (wn + nt * 8 + gid) * RS + kw + tig;
                bh[nt][0] = sBh[bidx];
                bh[nt][1] = sBh[bidx + 4];
                bl[nt][0] = sBl[bidx];
                bl[nt][1] = sBl[bidx + 4];
            }
#pragma unroll
            for (int mt = 0; mt < 4; mt++) {
                const int arow = wm + mt * 16 + (lane & 15);
                const uint32_t aoff = bufb + (uint32_t)(arow * RS + kw + (lane >> 4) * 4) * 4u;
                uint32_t ah0, ah1, ah2, ah3, al0, al1, al2, al3;
                ldsm4(ub + aoff,           ah0, ah1, ah2, ah3);
                ldsm4(ub + PLANE_B + aoff, al0, al1, al2, al3);
#pragma unroll
                for (int nt = 0; nt < 4; nt++) {
                    mma16(acc[mt][nt], ah0, ah1, ah2, ah3, bh[nt][0], bh[nt][1]);
                    mma16(acc[mt][nt], ah0, ah1, ah2, ah3, bl[nt][0], bl[nt][1]);
                    mma16(acc[mt][nt], al0, al1, al2, al3, bh[nt][0], bh[nt][1]);
                }
            }
        }
        __syncthreads();
    }

    float* Cb = C + (size_t)bym * BM * ldc + (size_t)bxn * BN;
#pragma unroll
    for (int mt = 0; mt < 4; mt++) {
        const int row = wm + mt * 16 + gid;
#pragma unroll
        for (int nt = 0; nt < 4; nt++) {
            const int col = wn + nt * 8 + 2 * tig;
            *reinterpret_cast<float2*>(Cb + (size_t)row * ldc + col) =
                make_float2(acc[mt][nt][0], acc[mt][nt][1]);
            *reinterpret_cast<float2*>(Cb + (size_t)(row + 8) * ldc + col) =
                make_float2(acc[mt][nt][2], acc[mt][nt][3]);
        }
    }
}

// Fused Q/K/V projections: grid.x = 24 (16 Q, 4 K, 4 V n-blocks).
__global__ __launch_bounds__(NTHREADS) void k_qkv() {
    const int bx = blockIdx.x;
    const __half *Bh, *Bl;
    float* O;
    int ldo, nb;
    if (bx < 16)      { Bh = g_wqh; Bl = g_wql; O = g_q; ldo = CDIM;  nb = bx; }
    else if (bx < 20) { Bh = g_wkh; Bl = g_wkl; O = g_k; ldo = KVDIM; nb = bx - 16; }
    else              { Bh = g_wvh; Bl = g_wvl; O = g_v; ldo = KVDIM; nb = bx - 20; }
    gemm_async_nt(g_xh, g_xl, CDIM, Bh, Bl, CDIM, O, ldo, CDIM, nb, blockIdx.y);
}
__global__ __launch_bounds__(NTHREADS) void k_oproj(float* __restrict__ out) {
    gemm_async_nt(g_ah, g_al, CDIM, g_woh, g_wol, CDIM, out, CDIM, CDIM,
                  blockIdx.x, blockIdx.y);
}

// ---------------------------------------------------------------------------
// RoPE + fp16 pre-split (scaled q, k) — unchanged from round 10.
// ---------------------------------------------------------------------------
__global__ void k_rope_split(const int* __restrict__ start_pos) {
    __shared__ float cs[HDIM / 2], sn[HDIM / 2];
    const int bt  = blockIdx.x;
    const int t   = bt & (SEQ - 1);
    const int tid = threadIdx.x;

    if (tid < HDIM / 2) {
        double inv = pow(10000.0, -(double)(2 * tid) / (double)HDIM);
        double ang = (double)(t + start_pos[0]) * inv;
        cs[tid] = (float)cos(ang);
        sn[tid] = (float)sin(ang);
    }
    __syncthreads();

    const float* qrow = g_q + (size_t)bt * CDIM;
    __half* qh = g_qh + (size_t)bt * CDIM;
    __half* ql = g_ql + (size_t)bt * CDIM;
    for (int idx = tid; idx < NHEAD * (HDIM / 2); idx += blockDim.x) {
        int h = idx >> 6, i = idx & 63;
        float x1 = qrow[h * HDIM + i];
        float x2 = qrow[h * HDIM + i + 64];
        float r1 = (x1 * cs[i] - x2 * sn[i]) * SCALE;
        float r2 = (x2 * cs[i] + x1 * sn[i]) * SCALE;
        __half h1 = __float2half_rn(r1);
        __half h2 = __float2half_rn(r2);
        qh[h * HDIM + i]      = h1;
        ql[h * HDIM + i]      = __float2half_rn(r1 - __half2float(h1));
        qh[h * HDIM + i + 64] = h2;
        ql[h * HDIM + i + 64] = __float2half_rn(r2 - __half2float(h2));
    }

    const float* krow = g_k + (size_t)bt * KVDIM;
    __half* kh = g_kh + (size_t)bt * KVDIM;
    __half* kl = g_kl + (size_t)bt * KVDIM;
    for (int idx = tid; idx < NKV * (HDIM / 2); idx += blockDim.x) {
        int h = idx >> 6, i = idx & 63;
        float x1 = krow[h * HDIM + i];
        float x2 = krow[h * HDIM + i + 64];
        float r1 = x1 * cs[i] - x2 * sn[i];
        float r2 = x2 * cs[i] + x1 * sn[i];
        __half h1 = __float2half_rn(r1);
        __half h2 = __float2half_rn(r2);
        kh[h * HDIM + i]      = h1;
        kl[h * HDIM + i]      = __float2half_rn(r1 - __half2float(h1));
        kh[h * HDIM + i + 64] = h2;
        kl[h * HDIM + i + 64] = __float2half_rn(r2 - __half2float(h2));
    }
}

// ---------------------------------------------------------------------------
// V transpose + split
// ---------------------------------------------------------------------------
__global__ void k_vt2() {
    __shared__ float tile[32][33];
    const int b  = blockIdx.z;
    const int t0 = blockIdx.x * 32;
    const int d0 = blockIdx.y * 32;
    const int tx = threadIdx.x, ty = threadIdx.y;
#pragma unroll
    for (int j = 0; j < 4; j++) {
        tile[ty + 8 * j][tx] =
            g_v[((size_t)b * SEQ + t0 + ty + 8 * j) * KVDIM + d0 + tx];
    }
    __syncthreads();
#pragma unroll
    for (int j = 0; j < 4; j++) {
        float v = tile[tx][ty + 8 * j];
        __half hh = __float2half_rn(v);
        size_t o = ((size_t)b * KVDIM + d0 + ty + 8 * j) * SEQ + t0 + tx;
        g_vth[o] = hh;
        g_vtl[o] = __float2half_rn(v - __half2float(hh));
    }
}

// ---------------------------------------------------------------------------
// Fused flash attention, staging pipelined via interleaved cp.async groups:
//   QK(kt) overlaps V(kt) arrival; K(kt+1) issues after QK; V(kt+1) after PV.
// grid (SEQ/128, BATCH*NHEAD), 256 threads, 1 CTA/SM.
// ---------------------------------------------------------------------------
__global__ __launch_bounds__(256, 1) void k_flash() {
    extern __shared__ uint32_t fsm[];
    const uint32_t ub = s2u(fsm);
    uint32_t* sKh = fsm + 2 * FPL;
    uint32_t* sKl = fsm + 3 * FPL;
    uint32_t* sVh = fsm + 4 * FPL;
    uint32_t* sVl = fsm + 5 * FPL;

    const int tid  = threadIdx.x;
    const int lane = tid & 31;
    const int warp = tid >> 5;
    const int gid  = lane >> 2;
    const int tig  = lane & 3;
    const int z = blockIdx.y, b = z >> 4, h = z & 15, g = h >> 2;

    const int r  = tid >> 1;
    const int ch = tid & 1;
    const uint32_t dwo = (uint32_t)(r * FW + ch * 32) * 4u;

    const __half* khb = g_kh + (size_t)b * SEQ * KVDIM + g * HDIM;
    const __half* klb = g_kl + (size_t)b * SEQ * KVDIM + g * HDIM;
    const __half* vhb = g_vth + ((size_t)b * KVDIM + g * HDIM) * SEQ;
    const __half* vlb = g_vtl + ((size_t)b * KVDIM + g * HDIM) * SEQ;

    // prologue: Q (group), K0 (group), V0 (group)
    {
        const __half* qh = g_qh + ((size_t)(b * SEQ + blockIdx.x * 128 + r)) * CDIM
                         + h * HDIM + ch * 64;
        const __half* ql = g_ql + ((size_t)(b * SEQ + blockIdx.x * 128 + r)) * CDIM
                         + h * HDIM + ch * 64;
#pragma unroll
        for (int j = 0; j < 8; j++) {
            cp16(ub + dwo + 16u * j,                      qh + 8 * j);
            cp16(ub + (uint32_t)FPL * 4u + dwo + 16u * j, ql + 8 * j);
        }
        CP_COMMIT();
        const __half* kh = khb + (size_t)r * KVDIM + ch * 64;
        const __half* kl = klb + (size_t)r * KVDIM + ch * 64;
#pragma unroll
        for (int j = 0; j < 8; j++) {
            cp16(ub + 2u * FPL * 4u + dwo + 16u * j, kh + 8 * j);
            cp16(ub + 3u * FPL * 4u + dwo + 16u * j, kl + 8 * j);
        }
        CP_COMMIT();
        const __half* vh = vhb + (size_t)r * SEQ + ch * 64;
        const __half* vl = vlb + (size_t)r * SEQ + ch * 64;
#pragma unroll
        for (int j = 0; j < 8; j++) {
            cp16(ub + 4u * FPL * 4u + dwo + 16u * j, vh + 8 * j);
            cp16(ub + 5u * FPL * 4u + dwo + 16u * j, vl + 8 * j);
        }
        CP_COMMIT();
    }

    float accO[16][4];
#pragma unroll
    for (int nt = 0; nt < 16; nt++)
#pragma unroll
        for (int q = 0; q < 4; q++) accO[nt][q] = 0.0f;
    float m0 = -INFINITY, m1 = -INFINITY, l0s = 0.0f, l1s = 0.0f;

#pragma unroll 1
    for (int kt = 0; kt < SEQ / 128; kt++) {
        // K(kt) ready (V(kt) may still be in flight)
        CP_WAIT1();
        __syncthreads();

        // S = Q.K^T
        float accS[16][4];
#pragma unroll
        for (int nt = 0; nt < 16; nt++)
#pragma unroll
            for (int q = 0; q < 4; q++) accS[nt][q] = 0.0f;

#pragma unroll
        for (int s = 0; s < 8; s++) {
            const uint32_t aoff =
                (uint32_t)((warp * 16 + (lane & 15)) * FW + s * 8 + (lane >> 4) * 4) * 4u;
            uint32_t qh0, qh1, qh2, qh3, ql0, ql1, ql2, ql3;
            ldsm4(ub + aoff,                      qh0, qh1, qh2, qh3);
            ldsm4(ub + (uint32_t)FPL * 4u + aoff, ql0, ql1, ql2, ql3);
#pragma unroll
            for (int nt = 0; nt < 16; nt++) {
                const int wi = (nt * 8 + gid) * FW + s * 8 + tig;
                uint32_t bh0 = sKh[wi], bh1 = sKh[wi + 4];
                uint32_t bl0 = sKl[wi], bl1 = sKl[wi + 4];
                mma16(accS[nt], qh0, qh1, qh2, qh3, bh0, bh1);
                mma16(accS[nt], qh0, qh1, qh2, qh3, bl0, bl1);
                mma16(accS[nt], ql0, ql1, ql2, ql3, bh0, bh1);
            }
        }
        __syncthreads();   // all warps done reading K planes

        if (kt + 1 < SEQ / 128) {   // prefetch K(kt+1) into the K planes
            const __half* kh = khb + (size_t)((kt + 1) * 128 + r) * KVDIM + ch * 64;
            const __half* kl = klb + (size_t)((kt + 1) * 128 + r) * KVDIM + ch * 64;
#pragma unroll
            for (int j = 0; j < 8; j++) {
                cp16(ub + 2u * FPL * 4u + dwo + 16u * j, kh + 8 * j);
                cp16(ub + 3u * FPL * 4u + dwo + 16u * j, kl + 8 * j);
            }
            CP_COMMIT();
        }

        // online softmax
        float r0 = -INFINITY, r1 = -INFINITY;
#pragma unroll
        for (int nt = 0; nt < 16; nt++) {
            r0 = fmaxf(r0, fmaxf(accS[nt][0], accS[nt][1]));
            r1 = fmaxf(r1, fmaxf(accS[nt][2], accS[nt][3]));
        }
        r0 = fmaxf(r0, __shfl_xor_sync(0xFFFFFFFFu, r0, 1));
        r0 = fmaxf(r0, __shfl_xor_sync(0xFFFFFFFFu, r0, 2));
        r1 = fmaxf(r1, __shfl_xor_sync(0xFFFFFFFFu, r1, 1));
        r1 = fmaxf(r1, __shfl_xor_sync(0xFFFFFFFFu, r1, 2));
        const float mn0 = fmaxf(m0, r0), mn1 = fmaxf(m1, r1);
        const float a0 = __expf(m0 - mn0), a1 = __expf(m1 - mn1);
        m0 = mn0; m1 = mn1;

        float s0 = 0.0f, s1 = 0.0f;
#pragma unroll
        for (int nt = 0; nt < 16; nt++) {
            accS[nt][0] = __expf(accS[nt][0] - mn0);
            accS[nt][1] = __expf(accS[nt][1] - mn0);
            accS[nt][2] = __expf(accS[nt][2] - mn1);
            accS[nt][3] = __expf(accS[nt][3] - mn1);
            s0 += accS[nt][0] + accS[nt][1];
            s1 += accS[nt][2] + accS[nt][3];
        }
        s0 += __shfl_xor_sync(0xFFFFFFFFu, s0, 1);
        s0 += __shfl_xor_sync(0xFFFFFFFFu, s0, 2);
        s1 += __shfl_xor_sync(0xFFFFFFFFu, s1, 1);
        s1 += __shfl_xor_sync(0xFFFFFFFFu, s1, 2);
        l0s = l0s * a0 + s0;
        l1s = l1s * a1 + s1;

#pragma unroll
        for (int nt = 0; nt < 16; nt++) {
            accO[nt][0] *= a0; accO[nt][1] *= a0;
            accO[nt][2] *= a1; accO[nt][3] *= a1;
        }

        // V(kt) ready (K(kt+1) may still be in flight)
        if (kt + 1 < SEQ / 128) CP_WAIT1(); else CP_WAIT0();
        __syncthreads();

        // O += P.V
#pragma unroll
        for (int s = 0; s < 8; s++) {
            uint32_t pa0, pa1, pa2, pa3, pl0, pl1, pl2, pl3;
            split2(accS[2 * s][0],     accS[2 * s][1],     pa0, pl0);
            split2(accS[2 * s][2],     accS[2 * s][3],     pa1, pl1);
            split2(accS[2 * s + 1][0], accS[2 * s + 1][1], pa2, pl2);
            split2(accS[2 * s + 1][2], accS[2 * s + 1][3], pa3, pl3);
#pragma unroll
            for (int nt = 0; nt < 16; nt++) {
                const int wi = (nt * 8 + gid) * FW + s * 8 + tig;
                uint32_t vh0 = sVh[wi], vh1 = sVh[wi + 4];
                uint32_t vl0 = sVl[wi], vl1 = sVl[wi + 4];
                mma16(accO[nt], pa0, pa1, pa2, pa3, vh0, vh1);
                mma16(accO[nt], pa0, pa1, pa2, pa3, vl0, vl1);
                mma16(accO[nt], pl0, pl1, pl2, pl3, vh0, vh1);
            }
        }
        __syncthreads();   // all warps done reading V planes

        if (kt + 1 < SEQ / 128) {   // prefetch V(kt+1)
            const __half* vh = vhb + (size_t)r * SEQ + (kt + 1) * 128 + ch * 64;
            const __half* vl = vlb + (size_t)r * SEQ + (kt + 1) * 128 + ch * 64;
#pragma unroll
            for (int j = 0; j < 8; j++) {
                cp16(ub + 4u * FPL * 4u + dwo + 16u * j, vh + 8 * j);
                cp16(ub + 5u * FPL * 4u + dwo + 16u * j, vl + 8 * j);
            }
            CP_COMMIT();
        }
    }

    // epilogue: O /= l, write split fp16 planes (consumed by o-proj)
    const float i0 = 1.0f / l0s, i1 = 1.0f / l1s;
    const int row0 = blockIdx.x * 128 + warp * 16 + gid;
    const size_t ob = ((size_t)(b * SEQ + row0)) * CDIM + h * HDIM;
#pragma unroll
    for (int nt = 0; nt < 16; nt++) {
        const int col = nt * 8 + 2 * tig;
        uint32_t hw, lw;
        split2(accO[nt][0] * i0, accO[nt][1] * i0, hw, lw);
        *reinterpret_cast<uint32_t*>(g_ah + ob + col) = hw;
        *reinterpret_cast<uint32_t*>(g_al + ob + col) = lw;
        split2(accO[nt][2] * i1, accO[nt][3] * i1, hw, lw);
        *reinterpret_cast<uint32_t*>(g_ah + ob + 8 * CDIM + col) = hw;
        *reinterpret_cast<uint32_t*>(g_al + ob + 8 * CDIM + col) = lw;
    }
}

// ---------------------------------------------------------------------------
// Entry point
// ---------------------------------------------------------------------------
extern "C" void kernel_launch(void* const* d_in, const int* in_sizes, int n_in,
                              void* d_out, int out_size) {
    const float* x  = (const float*)d_in[0];
    const float* Wq = (const float*)d_in[1];
    const float* Wk = (const float*)d_in[2];
    const float* Wv = (const float*)d_in[3];
    const float* Wo = (const float*)d_in[4];
    const int*   sp = (const int*)d_in[5];
    float* out = (float*)d_out;

    static int attr_set = 0;
    if (!attr_set) {
        cudaFuncSetAttribute(k_flash, cudaFuncAttributeMaxDynamicSharedMemorySize,
                             SMEM_FLASH);
        cudaFuncSetAttribute(k_qkv, cudaFuncAttributeMaxDynamicSharedMemorySize,
                             SMEM_PROJ);
        cudaFuncSetAttribute(k_oproj, cudaFuncAttributeMaxDynamicSharedMemorySize,
                             SMEM_PROJ);
        attr_set = 1;
    }

    // resolve device-symbol addresses for the split kernels
    __half *xh, *xl, *wqh, *wql, *wkh, *wkl, *wvh, *wvl, *woh, *wol;
    cudaGetSymbolAddress((void**)&xh,  g_xh);
    cudaGetSymbolAddress((void**)&xl,  g_xl);
    cudaGetSymbolAddress((void**)&wqh, g_wqh);
    cudaGetSymbolAddress((void**)&wql, g_wql);
    cudaGetSymbolAddress((void**)&wkh, g_wkh);
    cudaGetSymbolAddress((void**)&wkl, g_wkl);
    cudaGetSymbolAddress((void**)&wvh, g_wvh);
    cudaGetSymbolAddress((void**)&wvl, g_wvl);
    cudaGetSymbolAddress((void**)&woh, g_woh);
    cudaGetSymbolAddress((void**)&wol, g_wol);

    const int n4x = MROWS * CDIM / 4, n4q = CDIM * CDIM / 4, n4k = KVDIM * CDIM / 4;
    k_split<<<(n4x + 255) / 256, 256>>>((const float4*)x,  (uint2*)xh,  (uint2*)xl,  n4x);
    k_split<<<(n4q + 255) / 256, 256>>>((const float4*)Wq, (uint2*)wqh, (uint2*)wql, n4q);
    k_split<<<(n4k + 255) / 256, 256>>>((const float4*)Wk, (uint2*)wkh, (uint2*)wkl, n4k);
    k_split<<<(n4k + 255) / 256, 256>>>((const float4*)Wv, (uint2*)wvh, (uint2*)wvl, n4k);
    k_split<<<(n4q + 255) / 256, 256>>>((const float4*)Wo, (uint2*)woh, (uint2*)wol, n4q);

    k_qkv<<<dim3(24, MROWS / BM), NTHREADS, SMEM_PROJ>>>();
    k_rope_split<<<MROWS, 256>>>(sp);
    k_vt2<<<dim3(SEQ / 32, KVDIM / 32, BATCH), dim3(32, 8)>>>();
    k_flash<<<dim3(SEQ / 128, BATCH * NHEAD), 256, SMEM_FLASH>>>();
    k_oproj<<<dim3(CDIM / BN, MROWS / BM), NTHREADS, SMEM_PROJ>>>(out);
}

// round 13
// speedup vs baseline: 2.4177x; 1.0213x over previous
#include <cuda_runtime.h>
#include <cuda_fp16.h>
#include <math.h>
#include <stdint.h>

// Problem constants
#define BATCH   2
#define SEQ     2048
#define CDIM    2048
#define NHEAD   16
#define NKV     4
#define HDIM    128
#define MROWS   (BATCH * SEQ)          // 4096
#define KVDIM   (NKV * HDIM)           // 512
#define SCALE   0.08838834764831845f   // 1/sqrt(128)

// Projection GEMM tiling
#define BM 128
#define BN 128
#define BK 32
#define RS 20                          // words per smem row (16 data + 4 pad)
#define PLANE_W (128 * RS)
#define PLANE_B (PLANE_W * 4)          // 10240 B
#define SMEM_PROJ (2 * 4 * PLANE_B)    // 81920 B (double-buffered 4 planes)
#define NTHREADS 256

// Flash kernel smem: 6 planes of [128 rows x 68 words]
#define FW  68
#define FPL (128 * FW)
#define SMEM_FLASH (6 * FPL * 4)       // 208896 B

// ---------------------------------------------------------------------------
// Static device scratch
// ---------------------------------------------------------------------------
__device__ float  g_q[(size_t)MROWS * CDIM];             // fp32 q (pre-rope)
__device__ float  g_k[(size_t)MROWS * KVDIM];
__device__ float  g_v[(size_t)MROWS * KVDIM];
// pre-split fp16 hi/lo planes
__device__ __half g_xh[(size_t)MROWS * CDIM],  g_xl[(size_t)MROWS * CDIM];
__device__ __half g_wqh[(size_t)CDIM * CDIM],  g_wql[(size_t)CDIM * CDIM];
__device__ __half g_wkh[(size_t)KVDIM * CDIM], g_wkl[(size_t)KVDIM * CDIM];
__device__ __half g_wvh[(size_t)KVDIM * CDIM], g_wvl[(size_t)KVDIM * CDIM];
__device__ __half g_woh[(size_t)CDIM * CDIM],  g_wol[(size_t)CDIM * CDIM];
__device__ __half g_qh[(size_t)MROWS * CDIM],  g_ql[(size_t)MROWS * CDIM];
__device__ __half g_kh[(size_t)MROWS * KVDIM], g_kl[(size_t)MROWS * KVDIM];
__device__ __half g_vth[(size_t)BATCH * KVDIM * SEQ], g_vtl[(size_t)BATCH * KVDIM * SEQ];
__device__ __half g_ah[(size_t)MROWS * CDIM],  g_al[(size_t)MROWS * CDIM]; // attn out split

// ---------------------------------------------------------------------------
// Helpers
// ---------------------------------------------------------------------------
__device__ __forceinline__ uint32_t s2u(const void* p) {
    uint32_t a;
    asm("{ .reg .u64 t; cvta.to.shared.u64 t, %1; cvt.u32.u64 %0, t; }" : "=r"(a) : "l"(p));
    return a;
}
__device__ __forceinline__ void split2(float x, float y, uint32_t& hw, uint32_t& lw) {
    __half2 h = __floats2half2_rn(x, y);
    float2 hf = __half22float2(h);
    __half2 l = __floats2half2_rn(x - hf.x, y - hf.y);
    hw = *reinterpret_cast<uint32_t*>(&h);
    lw = *reinterpret_cast<uint32_t*>(&l);
}
__device__ __forceinline__ void ldsm4(uint32_t addr, uint32_t& r0, uint32_t& r1,
                                      uint32_t& r2, uint32_t& r3) {
    asm volatile("ldmatrix.sync.aligned.m8n8.x4.shared.b16 {%0,%1,%2,%3}, [%4];"
                 : "=r"(r0), "=r"(r1), "=r"(r2), "=r"(r3) : "r"(addr));
}
__device__ __forceinline__ void mma16(float* d, uint32_t a0, uint32_t a1, uint32_t a2,
                                      uint32_t a3, uint32_t b0, uint32_t b1) {
    asm volatile(
        "mma.sync.aligned.m16n8k16.row.col.f32.f16.f16.f32 "
        "{%0,%1,%2,%3}, {%4,%5,%6,%7}, {%8,%9}, {%0,%1,%2,%3};"
        : "+f"(d[0]), "+f"(d[1]), "+f"(d[2]), "+f"(d[3])
        : "r"(a0), "r"(a1), "r"(a2), "r"(a3), "r"(b0), "r"(b1));
}
__device__ __forceinline__ void cp16(uint32_t dst, const void* src) {
    asm volatile("cp.async.cg.shared.global [%0], [%1], 16;" :: "r"(dst), "l"(src));
}
#define CP_COMMIT() asm volatile("cp.async.commit_group;" ::: "memory")
#define CP_WAIT0()  asm volatile("cp.async.wait_group 0;" ::: "memory")
#define CP_WAIT1()  asm volatile("cp.async.wait_group 1;" ::: "memory")

// ---------------------------------------------------------------------------
// Elementwise fp16 hi/lo split
// ---------------------------------------------------------------------------
__global__ __launch_bounds__(256) void k_split(const float4* __restrict__ src,
                                               uint2* __restrict__ h,
                                               uint2* __restrict__ l, int n4) {
    int i = blockIdx.x * 256 + threadIdx.x;
    if (i >= n4) return;
    float4 v = src[i];
    uint32_t h0, l0, h1, l1;
    split2(v.x, v.y, h0, l0);
    split2(v.z, v.w, h1, l1);
    h[i] = make_uint2(h0, h1);
    l[i] = make_uint2(l0, l1);
}

// ---------------------------------------------------------------------------
// NT GEMM core on pre-split fp16 planes, cp.async double-buffered staging.
// ---------------------------------------------------------------------------
__device__ void gemm_async_nt(const __half* __restrict__ Ah, const __half* __restrict__ Al,
                              int lda,
                              const __half* __restrict__ Bh, const __half* __restrict__ Bl,
                              int ldb,
                              float* __restrict__ C, int ldc,
                              int K, int bxn, int bym)
{
    extern __shared__ uint32_t psm[];
    const uint32_t ub = s2u(psm);

    const int tid  = threadIdx.x;
    const int lane = tid & 31;
    const int warp = tid >> 5;
    const int gid  = lane >> 2;
    const int tig  = lane & 3;
    const int wm   = (warp & 1) * 64;
    const int wn   = (warp >> 1) * 32;

    const int r  = tid >> 1;
    const int hf = tid & 1;
    const __half* pAh = Ah + (size_t)(bym * BM + r) * lda + hf * 16;
    const __half* pAl = Al + (size_t)(bym * BM + r) * lda + hf * 16;
    const __half* pBh = Bh + (size_t)(bxn * BN + r) * ldb + hf * 16;
    const __half* pBl = Bl + (size_t)(bxn * BN + r) * ldb + hf * 16;
    const uint32_t dst0 = ub + (uint32_t)(r * RS + hf * 8) * 4u;

    float acc[4][4][4];
#pragma unroll
    for (int i = 0; i < 4; i++)
#pragma unroll
        for (int j = 0; j < 4; j++)
#pragma unroll
            for (int q = 0; q < 4; q++) acc[i][j][q] = 0.0f;

    const int NCC = K / BK;

    {
        cp16(dst0,                 pAh);
        cp16(dst0 + 16,            pAh + 8);
        cp16(dst0 + PLANE_B,       pAl);
        cp16(dst0 + PLANE_B + 16,  pAl + 8);
        cp16(dst0 + 2 * PLANE_B,      pBh);
        cp16(dst0 + 2 * PLANE_B + 16, pBh + 8);
        cp16(dst0 + 3 * PLANE_B,      pBl);
        cp16(dst0 + 3 * PLANE_B + 16, pBl + 8);
        CP_COMMIT();
    }

    for (int kc = 0; kc < NCC; kc++) {
        if (kc + 1 < NCC) {
            const uint32_t d = dst0 + (uint32_t)(((kc + 1) & 1) * 4 * PLANE_B);
            const int ko = (kc + 1) * BK;
            cp16(d,                 pAh + ko);
            cp16(d + 16,            pAh + ko + 8);
            cp16(d + PLANE_B,       pAl + ko);
            cp16(d + PLANE_B + 16,  pAl + ko + 8);
            cp16(d + 2 * PLANE_B,      pBh + ko);
            cp16(d + 2 * PLANE_B + 16, pBh + ko + 8);
            cp16(d + 3 * PLANE_B,      pBl + ko);
            cp16(d + 3 * PLANE_B + 16, pBl + ko + 8);
            CP_COMMIT();
            CP_WAIT1();
        } else {
            CP_WAIT0();
        }
        __syncthreads();

        const int bufw = (kc & 1) * 4 * PLANE_W;
        const uint32_t bufb = (uint32_t)(kc & 1) * 4u * PLANE_B;
        const uint32_t* sBh = psm + bufw + 2 * PLANE_W;
        const uint32_t* sBl = psm + bufw + 3 * PLANE_W;

#pragma unroll
        for (int ks = 0; ks < 2; ks++) {
            const int kw = ks * 8;
            uint32_t bh[4][2], bl[4][2];
#pragma unroll
            for (int nt = 0; nt < 4; nt++) {
                const int bidx = (wn + nt * 8 + gid) * RS + kw + tig;
                bh[nt][0] = sBh[bidx];
                bh[nt][1] = sBh[bidx + 4];
                bl[nt][0] = sBl[bidx];
                bl[nt][1] = sBl[bidx + 4];
            }
#pragma unroll
            for (int mt = 0; mt < 4; mt++) {
                const int arow = wm + mt * 16 + (lane & 15);
                const uint32_t aoff = bufb + (uint32_t)(arow * RS + kw + (lane >> 4) * 4) * 4u;
                uint32_t ah0, ah1, ah2, ah3, al0, al1, al2, al3;
                ldsm4(ub + aoff,           ah0, ah1, ah2, ah3);
                ldsm4(ub + PLANE_B + aoff, al0, al1, al2, al3);
#pragma unroll
                for (int nt = 0; nt < 4; nt++) {
                    mma16(acc[mt][nt], ah0, ah1, ah2, ah3, bh[nt][0], bh[nt][1]);
                    mma16(acc[mt][nt], ah0, ah1, ah2, ah3, bl[nt][0], bl[nt][1]);
                    mma16(acc[mt][nt], al0, al1, al2, al3, bh[nt][0], bh[nt][1]);
                }
            }
        }
        __syncthreads();
    }

    float* Cb = C + (size_t)bym * BM * ldc + (size_t)bxn * BN;
#pragma unroll
    for (int mt = 0; mt < 4; mt++) {
        const int row = wm + mt * 16 + gid;
#pragma unroll
        for (int nt = 0; nt < 4; nt++) {
            const int col = wn + nt * 8 + 2 * tig;
            *reinterpret_cast<float2*>(Cb + (size_t)row * ldc + col) =
                make_float2(acc[mt][nt][0], acc[mt][nt][1]);
            *reinterpret_cast<float2*>(Cb + (size_t)(row + 8) * ldc + col) =
                make_float2(acc[mt][nt][2], acc[mt][nt][3]);
        }
    }
}

// Fused Q/K/V projections: grid.x = 24 (16 Q, 4 K, 4 V n-blocks). 2 CTAs/SM.
__global__ __launch_bounds__(NTHREADS, 2) void k_qkv() {
    const int bx = blockIdx.x;
    const __half *Bh, *Bl;
    float* O;
    int ldo, nb;
    if (bx < 16)      { Bh = g_wqh; Bl = g_wql; O = g_q; ldo = CDIM;  nb = bx; }
    else if (bx < 20) { Bh = g_wkh; Bl = g_wkl; O = g_k; ldo = KVDIM; nb = bx - 16; }
    else              { Bh = g_wvh; Bl = g_wvl; O = g_v; ldo = KVDIM; nb = bx - 20; }
    gemm_async_nt(g_xh, g_xl, CDIM, Bh, Bl, CDIM, O, ldo, CDIM, nb, blockIdx.y);
}
__global__ __launch_bounds__(NTHREADS, 2) void k_oproj(float* __restrict__ out) {
    gemm_async_nt(g_ah, g_al, CDIM, g_woh, g_wol, CDIM, out, CDIM, CDIM,
                  blockIdx.x, blockIdx.y);
}

// ---------------------------------------------------------------------------
// RoPE + fp16 pre-split (scaled q, k)
// ---------------------------------------------------------------------------
__global__ void k_rope_split(const int* __restrict__ start_pos) {
    __shared__ float cs[HDIM / 2], sn[HDIM / 2];
    const int bt  = blockIdx.x;
    const int t   = bt & (SEQ - 1);
    const int tid = threadIdx.x;

    if (tid < HDIM / 2) {
        double inv = pow(10000.0, -(double)(2 * tid) / (double)HDIM);
        double ang = (double)(t + start_pos[0]) * inv;
        cs[tid] = (float)cos(ang);
        sn[tid] = (float)sin(ang);
    }
    __syncthreads();

    const float* qrow = g_q + (size_t)bt * CDIM;
    __half* qh = g_qh + (size_t)bt * CDIM;
    __half* ql = g_ql + (size_t)bt * CDIM;
    for (int idx = tid; idx < NHEAD * (HDIM / 2); idx += blockDim.x) {
        int h = idx >> 6, i = idx & 63;
        float x1 = qrow[h * HDIM + i];
        float x2 = qrow[h * HDIM + i + 64];
        float r1 = (x1 * cs[i] - x2 * sn[i]) * SCALE;
        float r2 = (x2 * cs[i] + x1 * sn[i]) * SCALE;
        __half h1 = __float2half_rn(r1);
        __half h2 = __float2half_rn(r2);
        qh[h * HDIM + i]      = h1;
        ql[h * HDIM + i]      = __float2half_rn(r1 - __half2float(h1));
        qh[h * HDIM + i + 64] = h2;
        ql[h * HDIM + i + 64] = __float2half_rn(r2 - __half2float(h2));
    }

    const float* krow = g_k + (size_t)bt * KVDIM;
    __half* kh = g_kh + (size_t)bt * KVDIM;
    __half* kl = g_kl + (size_t)bt * KVDIM;
    for (int idx = tid; idx < NKV * (HDIM / 2); idx += blockDim.x) {
        int h = idx >> 6, i = idx & 63;
        float x1 = krow[h * HDIM + i];
        float x2 = krow[h * HDIM + i + 64];
        float r1 = x1 * cs[i] - x2 * sn[i];
        float r2 = x2 * cs[i] + x1 * sn[i];
        __half h1 = __float2half_rn(r1);
        __half h2 = __float2half_rn(r2);
        kh[h * HDIM + i]      = h1;
        kl[h * HDIM + i]      = __float2half_rn(r1 - __half2float(h1));
        kh[h * HDIM + i + 64] = h2;
        kl[h * HDIM + i + 64] = __float2half_rn(r2 - __half2float(h2));
    }
}

// ---------------------------------------------------------------------------
// V transpose + split
// ---------------------------------------------------------------------------
__global__ void k_vt2() {
    __shared__ float tile[32][33];
    const int b  = blockIdx.z;
    const int t0 = blockIdx.x * 32;
    const int d0 = blockIdx.y * 32;
    const int tx = threadIdx.x, ty = threadIdx.y;
#pragma unroll
    for (int j = 0; j < 4; j++) {
        tile[ty + 8 * j][tx] =
            g_v[((size_t)b * SEQ + t0 + ty + 8 * j) * KVDIM + d0 + tx];
    }
    __syncthreads();
#pragma unroll
    for (int j = 0; j < 4; j++) {
        float v = tile[tx][ty + 8 * j];
        __half hh = __float2half_rn(v);
        size_t o = ((size_t)b * KVDIM + d0 + ty + 8 * j) * SEQ + t0 + tx;
        g_vth[o] = hh;
        g_vtl[o] = __float2half_rn(v - __half2float(hh));
    }
}

// ---------------------------------------------------------------------------
// Fused flash attention: pipelined cp.async staging; B-fragments via
// NON-trans ldmatrix.x4 on [n][k]-stored planes (round-12 used .trans — wrong
// pairing axis; non-trans gives b0/b1 = k-pairs per n-row, the exact B frag).
// grid (SEQ/128, BATCH*NHEAD), 256 threads, 1 CTA/SM.
// ---------------------------------------------------------------------------
__global__ __launch_bounds__(256, 1) void k_flash() {
    extern __shared__ uint32_t fsm[];
    const uint32_t ub = s2u(fsm);

    const int tid  = threadIdx.x;
    const int lane = tid & 31;
    const int warp = tid >> 5;
    const int gid  = lane >> 2;
    const int tig  = lane & 3;
    const int z = blockIdx.y, b = z >> 4, h = z & 15, g = h >> 2;

    const int r  = tid >> 1;
    const int ch = tid & 1;
    const uint32_t dwo = (uint32_t)(r * FW + ch * 32) * 4u;

    // Non-trans ldmatrix.x4 B-fragment addressing on [n][k] planes:
    //   matrix m = lane>>3:  m0 = n rows base..+7 @ k-words 0-3
    //                        m1 = same rows       @ k-words 4-7
    //                        m2 = rows +8         @ k-words 0-3
    //                        m3 = rows +8         @ k-words 4-7
    //   => r0,r1 = (b0,b1) of n-tile(base), r2,r3 = (b0,b1) of n-tile(base+8)
    const uint32_t btrow = (uint32_t)((lane & 7) + ((lane >> 4) << 3));
    const uint32_t btcol = (uint32_t)(((lane >> 3) & 1) << 2);

    const __half* khb = g_kh + (size_t)b * SEQ * KVDIM + g * HDIM;
    const __half* klb = g_kl + (size_t)b * SEQ * KVDIM + g * HDIM;
    const __half* vhb = g_vth + ((size_t)b * KVDIM + g * HDIM) * SEQ;
    const __half* vlb = g_vtl + ((size_t)b * KVDIM + g * HDIM) * SEQ;

    // prologue: Q (group), K0 (group), V0 (group)
    {
        const __half* qh = g_qh + ((size_t)(b * SEQ + blockIdx.x * 128 + r)) * CDIM
                         + h * HDIM + ch * 64;
        const __half* ql = g_ql + ((size_t)(b * SEQ + blockIdx.x * 128 + r)) * CDIM
                         + h * HDIM + ch * 64;
#pragma unroll
        for (int j = 0; j < 8; j++) {
            cp16(ub + dwo + 16u * j,                      qh + 8 * j);
            cp16(ub + (uint32_t)FPL * 4u + dwo + 16u * j, ql + 8 * j);
        }
        CP_COMMIT();
        const __half* kh = khb + (size_t)r * KVDIM + ch * 64;
        const __half* kl = klb + (size_t)r * KVDIM + ch * 64;
#pragma unroll
        for (int j = 0; j < 8; j++) {
            cp16(ub + 2u * FPL * 4u + dwo + 16u * j, kh + 8 * j);
            cp16(ub + 3u * FPL * 4u + dwo + 16u * j, kl + 8 * j);
        }
        CP_COMMIT();
        const __half* vh = vhb + (size_t)r * SEQ + ch * 64;
        const __half* vl = vlb + (size_t)r * SEQ + ch * 64;
#pragma unroll
        for (int j = 0; j < 8; j++) {
            cp16(ub + 4u * FPL * 4u + dwo + 16u * j, vh + 8 * j);
            cp16(ub + 5u * FPL * 4u + dwo + 16u * j, vl + 8 * j);
        }
        CP_COMMIT();
    }

    float accO[16][4];
#pragma unroll
    for (int nt = 0; nt < 16; nt++)
#pragma unroll
        for (int q = 0; q < 4; q++) accO[nt][q] = 0.0f;
    float m0 = -INFINITY, m1 = -INFINITY, l0s = 0.0f, l1s = 0.0f;

#pragma unroll 1
    for (int kt = 0; kt < SEQ / 128; kt++) {
        // K(kt) ready (V(kt) may still be in flight)
        CP_WAIT1();
        __syncthreads();

        // S = Q.K^T
        float accS[16][4];
#pragma unroll
        for (int nt = 0; nt < 16; nt++)
#pragma unroll
            for (int q = 0; q < 4; q++) accS[nt][q] = 0.0f;

#pragma unroll
        for (int s = 0; s < 8; s++) {
            const int kw = s * 8;
            const uint32_t aoff =
                (uint32_t)((warp * 16 + (lane & 15)) * FW + kw + (lane >> 4) * 4) * 4u;
            uint32_t qh0, qh1, qh2, qh3, ql0, ql1, ql2, ql3;
            ldsm4(ub + aoff,                      qh0, qh1, qh2, qh3);
            ldsm4(ub + (uint32_t)FPL * 4u + aoff, ql0, ql1, ql2, ql3);
            const uint32_t bbase = ub + 2u * FPL * 4u
                                 + (btrow * FW + (uint32_t)kw + btcol) * 4u;
#pragma unroll
            for (int j = 0; j < 8; j++) {
                const uint32_t ba = bbase + (uint32_t)(16 * j * FW) * 4u;
                uint32_t kh0, kh1, kh2, kh3, kl0, kl1, kl2, kl3;
                ldsm4(ba,                      kh0, kh1, kh2, kh3);
                ldsm4(ba + (uint32_t)FPL * 4u, kl0, kl1, kl2, kl3);
                mma16(accS[2 * j],     qh0, qh1, qh2, qh3, kh0, kh1);
                mma16(accS[2 * j],     qh0, qh1, qh2, qh3, kl0, kl1);
                mma16(accS[2 * j],     ql0, ql1, ql2, ql3, kh0, kh1);
                mma16(accS[2 * j + 1], qh0, qh1, qh2, qh3, kh2, kh3);
                mma16(accS[2 * j + 1], qh0, qh1, qh2, qh3, kl2, kl3);
                mma16(accS[2 * j + 1], ql0, ql1, ql2, ql3, kh2, kh3);
            }
        }
        __syncthreads();   // all warps done reading K planes

        if (kt + 1 < SEQ / 128) {   // prefetch K(kt+1)
            const __half* kh = khb + (size_t)((kt + 1) * 128 + r) * KVDIM + ch * 64;
            const __half* kl = klb + (size_t)((kt + 1) * 128 + r) * KVDIM + ch * 64;
#pragma unroll
            for (int j = 0; j < 8; j++) {
                cp16(ub + 2u * FPL * 4u + dwo + 16u * j, kh + 8 * j);
                cp16(ub + 3u * FPL * 4u + dwo + 16u * j, kl + 8 * j);
            }
            CP_COMMIT();
        }

        // online softmax (rows g and g+8 of this warp's 16)
        float r0 = -INFINITY, r1 = -INFINITY;
#pragma unroll
        for (int nt = 0; nt < 16; nt++) {
            r0 = fmaxf(r0, fmaxf(accS[nt][0], accS[nt][1]));
            r1 = fmaxf(r1, fmaxf(accS[nt][2], accS[nt][3]));
        }
        r0 = fmaxf(r0, __shfl_xor_sync(0xFFFFFFFFu, r0, 1));
        r0 = fmaxf(r0, __shfl_xor_sync(0xFFFFFFFFu, r0, 2));
        r1 = fmaxf(r1, __shfl_xor_sync(0xFFFFFFFFu, r1, 1));
        r1 = fmaxf(r1, __shfl_xor_sync(0xFFFFFFFFu, r1, 2));
        const float mn0 = fmaxf(m0, r0), mn1 = fmaxf(m1, r1);
        const float a0 = __expf(m0 - mn0), a1 = __expf(m1 - mn1);
        m0 = mn0; m1 = mn1;

        float s0 = 0.0f, s1 = 0.0f;
#pragma unroll
        for (int nt = 0; nt < 16; nt++) {
            accS[nt][0] = __expf(accS[nt][0] - mn0);
            accS[nt][1] = __expf(accS[nt][1] - mn0);
            accS[nt][2] = __expf(accS[nt][2] - mn1);
            accS[nt][3] = __expf(accS[nt][3] - mn1);
            s0 += accS[nt][0] + accS[nt][1];
            s1 += accS[nt][2] + accS[nt][3];
        }
        s0 += __shfl_xor_sync(0xFFFFFFFFu, s0, 1);
        s0 += __shfl_xor_sync(0xFFFFFFFFu, s0, 2);
        s1 += __shfl_xor_sync(0xFFFFFFFFu, s1, 1);
        s1 += __shfl_xor_sync(0xFFFFFFFFu, s1, 2);
        l0s = l0s * a0 + s0;
        l1s = l1s * a1 + s1;

#pragma unroll
        for (int nt = 0; nt < 16; nt++) {
            accO[nt][0] *= a0; accO[nt][1] *= a0;
            accO[nt][2] *= a1; accO[nt][3] *= a1;
        }

        // V(kt) ready (K(kt+1) may still be in flight)
        if (kt + 1 < SEQ / 128) CP_WAIT1(); else CP_WAIT0();
        __syncthreads();

        // O += P.V
#pragma unroll
        for (int s = 0; s < 8; s++) {
            uint32_t pa0, pa1, pa2, pa3, pl0, pl1, pl2, pl3;
            split2(accS[2 * s][0],     accS[2 * s][1],     pa0, pl0);
            split2(accS[2 * s][2],     accS[2 * s][3],     pa1, pl1);
            split2(accS[2 * s + 1][0], accS[2 * s + 1][1], pa2, pl2);
            split2(accS[2 * s + 1][2], accS[2 * s + 1][3], pa3, pl3);
            const uint32_t vbase = ub + 4u * FPL * 4u
                                 + (btrow * FW + (uint32_t)(s * 8) + btcol) * 4u;
#pragma unroll
            for (int j = 0; j < 8; j++) {
                const uint32_t va = vbase + (uint32_t)(16 * j * FW) * 4u;
                uint32_t vh0, vh1, vh2, vh3, vl0, vl1, vl2, vl3;
                ldsm4(va,                      vh0, vh1, vh2, vh3);
                ldsm4(va + (uint32_t)FPL * 4u, vl0, vl1, vl2, vl3);
                mma16(accO[2 * j],     pa0, pa1, pa2, pa3, vh0, vh1);
                mma16(accO[2 * j],     pa0, pa1, pa2, pa3, vl0, vl1);
                mma16(accO[2 * j],     pl0, pl1, pl2, pl3, vh0, vh1);
                mma16(accO[2 * j + 1], pa0, pa1, pa2, pa3, vh2, vh3);
                mma16(accO[2 * j + 1], pa0, pa1, pa2, pa3, vl2, vl3);
                mma16(accO[2 * j + 1], pl0, pl1, pl2, pl3, vh2, vh3);
            }
        }
        __syncthreads();   // all warps done reading V planes

        if (kt + 1 < SEQ / 128) {   // prefetch V(kt+1)
            const __half* vh = vhb + (size_t)r * SEQ + (kt + 1) * 128 + ch * 64;
            const __half* vl = vlb + (size_t)r * SEQ + (kt + 1) * 128 + ch * 64;
#pragma unroll
            for (int j = 0; j < 8; j++) {
                cp16(ub + 4u * FPL * 4u + dwo + 16u * j, vh + 8 * j);
                cp16(ub + 5u * FPL * 4u + dwo + 16u * j, vl + 8 * j);
            }
            CP_COMMIT();
        }
    }

    // epilogue: O /= l, write split fp16 planes (consumed by o-proj)
    const float i0 = 1.0f / l0s, i1 = 1.0f / l1s;
    const int row0 = blockIdx.x * 128 + warp * 16 + gid;
    const size_t ob = ((size_t)(b * SEQ + row0)) * CDIM + h * HDIM;
#pragma unroll
    for (int nt = 0; nt < 16; nt++) {
        const int col = nt * 8 + 2 * tig;
        uint32_t hw, lw;
        split2(accO[nt][0] * i0, accO[nt][1] * i0, hw, lw);
        *reinterpret_cast<uint32_t*>(g_ah + ob + col) = hw;
        *reinterpret_cast<uint32_t*>(g_al + ob + col) = lw;
        split2(accO[nt][2] * i1, accO[nt][3] * i1, hw, lw);
        *reinterpret_cast<uint32_t*>(g_ah + ob + 8 * CDIM + col) = hw;
        *reinterpret_cast<uint32_t*>(g_al + ob + 8 * CDIM + col) = lw;
    }
}

// ---------------------------------------------------------------------------
// Entry point
// ---------------------------------------------------------------------------
extern "C" void kernel_launch(void* const* d_in, const int* in_sizes, int n_in,
                              void* d_out, int out_size) {
    const float* x  = (const float*)d_in[0];
    const float* Wq = (const float*)d_in[1];
    const float* Wk = (const float*)d_in[2];
    const float* Wv = (const float*)d_in[3];
    const float* Wo = (const float*)d_in[4];
    const int*   sp = (const int*)d_in[5];
    float* out = (float*)d_out;

    static int attr_set = 0;
    if (!attr_set) {
        cudaFuncSetAttribute(k_flash, cudaFuncAttributeMaxDynamicSharedMemorySize,
                             SMEM_FLASH);
        cudaFuncSetAttribute(k_qkv, cudaFuncAttributeMaxDynamicSharedMemorySize,
                             SMEM_PROJ);
        cudaFuncSetAttribute(k_oproj, cudaFuncAttributeMaxDynamicSharedMemorySize,
                             SMEM_PROJ);
        attr_set = 1;
    }

    __half *xh, *xl, *wqh, *wql, *wkh, *wkl, *wvh, *wvl, *woh, *wol;
    cudaGetSymbolAddress((void**)&xh,  g_xh);
    cudaGetSymbolAddress((void**)&xl,  g_xl);
    cudaGetSymbolAddress((void**)&wqh, g_wqh);
    cudaGetSymbolAddress((void**)&wql, g_wql);
    cudaGetSymbolAddress((void**)&wkh, g_wkh);
    cudaGetSymbolAddress((void**)&wkl, g_wkl);
    cudaGetSymbolAddress((void**)&wvh, g_wvh);
    cudaGetSymbolAddress((void**)&wvl, g_wvl);
    cudaGetSymbolAddress((void**)&woh, g_woh);
    cudaGetSymbolAddress((void**)&wol, g_wol);

    const int n4x = MROWS * CDIM / 4, n4q = CDIM * CDIM / 4, n4k = KVDIM * CDIM / 4;
    k_split<<<(n4x + 255) / 256, 256>>>((const float4*)x,  (uint2*)xh,  (uint2*)xl,  n4x);
    k_split<<<(n4q + 255) / 256, 256>>>((const float4*)Wq, (uint2*)wqh, (uint2*)wql, n4q);
    k_split<<<(n4k + 255) / 256, 256>>>((const float4*)Wk, (uint2*)wkh, (uint2*)wkl, n4k);
    k_split<<<(n4k + 255) / 256, 256>>>((const float4*)Wv, (uint2*)wvh, (uint2*)wvl, n4k);
    k_split<<<(n4q + 255) / 256, 256>>>((const float4*)Wo, (uint2*)woh, (uint2*)wol, n4q);

    k_qkv<<<dim3(24, MROWS / BM), NTHREADS, SMEM_PROJ>>>();
    k_rope_split<<<MROWS, 256>>>(sp);
    k_vt2<<<dim3(SEQ / 32, KVDIM / 32, BATCH), dim3(32, 8)>>>();
    k_flash<<<dim3(SEQ / 128, BATCH * NHEAD), 256, SMEM_FLASH>>>();
    k_oproj<<<dim3(CDIM / BN, MROWS / BM), NTHREADS, SMEM_PROJ>>>(out);
}